// round 12
// baseline (speedup 1.0000x reference)
#include <cuda_runtime.h>
#include <cuda_fp16.h>
#include <math.h>
#include <stdint.h>

// Problem dims
#define BD   2
#define TD   2048
#define CD   1024
#define HN   16
#define HD   64
#define DFFD 4096
#define NT   (BD * TD)   // 4096 tokens

// ---------------------------------------------------------------------------
// Scratch (device globals)
// ---------------------------------------------------------------------------
__device__ float  g_x2 [(size_t)NT * CD];
__device__ __half g_th  [(size_t)NT * CD];
__device__ __half g_t2h [(size_t)NT * CD];
__device__ __half g_qh  [(size_t)NT * CD];
__device__ __half g_kh  [(size_t)NT * CD];
__device__ __half g_vt  [(size_t)CD * NT];    // V transposed [dim][token]
__device__ __half g_ctxh[(size_t)NT * CD];
__device__ __half g_hh  [(size_t)NT * DFFD];
// k-pair-packed fp16 weights
__device__ __half2 g_wqp[(CD/2) * CD];
__device__ __half2 g_wkp[(CD/2) * CD];
__device__ __half2 g_wvp[(CD/2) * CD];
__device__ __half2 g_wop[(CD/2) * CD];
__device__ __half2 g_wep[(CD/2) * DFFD];
__device__ __half2 g_wdp[(DFFD/2) * CD];

// ---------------------------------------------------------------------------
// Helpers
// ---------------------------------------------------------------------------
__device__ __forceinline__ void cp16(uint32_t smem_dst, const void* gptr) {
    asm volatile("cp.async.cg.shared.global [%0], [%1], 16;\n"
                 :: "r"(smem_dst), "l"(gptr));
}
__device__ __forceinline__ void cp_commit() {
    asm volatile("cp.async.commit_group;\n" ::: "memory");
}
template <int N>
__device__ __forceinline__ void cp_wait() {
    asm volatile("cp.async.wait_group %0;\n" :: "n"(N) : "memory");
}
__device__ __forceinline__ void mma_f16(float* c, const uint32_t* a, const uint32_t* b) {
    asm volatile(
        "mma.sync.aligned.m16n8k16.row.col.f32.f16.f16.f32 "
        "{%0,%1,%2,%3},{%4,%5,%6,%7},{%8,%9},{%0,%1,%2,%3};"
        : "+f"(c[0]), "+f"(c[1]), "+f"(c[2]), "+f"(c[3])
        : "r"(a[0]), "r"(a[1]), "r"(a[2]), "r"(a[3]), "r"(b[0]), "r"(b[1]));
}
__device__ __forceinline__ void ldsm4(uint32_t* r, uint32_t addr) {
    asm volatile(
        "ldmatrix.sync.aligned.m8n8.x4.shared.b16 {%0,%1,%2,%3}, [%4];"
        : "=r"(r[0]), "=r"(r[1]), "=r"(r[2]), "=r"(r[3]) : "r"(addr));
}
__device__ __forceinline__ uint32_t h2scale(uint32_t w, __half2 s) {
    __half2 a = *(__half2*)&w;
    a = __hmul2(a, s);
    return *(uint32_t*)&a;
}

// ---------------------------------------------------------------------------
// Fused weight conversion (one launch)
// ---------------------------------------------------------------------------
__global__ __launch_bounds__(256) void wconv_all(
    const float* __restrict__ Wq, const float* __restrict__ Wk,
    const float* __restrict__ Wv, const float* __restrict__ Wo,
    const float* __restrict__ We, const float* __restrict__ Wd,
    __half2* __restrict__ oq, __half2* __restrict__ ok,
    __half2* __restrict__ ov, __half2* __restrict__ oo,
    __half2* __restrict__ oe, __half2* __restrict__ od)
{
    int idx = blockIdx.x * 256 + threadIdx.x;
    const float* W;
    __half2* out;
    int nshift, i;
    if (idx < (1 << 21)) {
        const int m = idx >> 19;
        i = idx & ((1 << 19) - 1);
        W   = (m == 0) ? Wq : (m == 1) ? Wk : (m == 2) ? Wv : Wo;
        out = (m == 0) ? oq : (m == 1) ? ok : (m == 2) ? ov : oo;
        nshift = 10;
    } else if (idx < (2 << 21)) {
        i = idx - (1 << 21);
        W = We; out = oe; nshift = 12;
    } else {
        i = idx - (2 << 21);
        W = Wd; out = od; nshift = 10;
    }
    const int kk = i >> nshift;
    const int n  = i & ((1 << nshift) - 1);
    const size_t base = ((size_t)(2 * kk) << nshift) + n;
    out[i] = __floats2half2_rn(W[base], W[base + ((size_t)1 << nshift)]);
}

// ---------------------------------------------------------------------------
// Fused double LayerNorm -> fp16 out
// ---------------------------------------------------------------------------
__global__ __launch_bounds__(256) void ln2_kernel(
    const float* __restrict__ x,
    const float* __restrict__ ga, const float* __restrict__ ba,
    const float* __restrict__ gb, const float* __restrict__ bb,
    __half* __restrict__ out)
{
    __shared__ float red[16];
    __shared__ float bc[2];
    const int row = blockIdx.x, tid = threadIdx.x;
    const float4 v = *(const float4*)(x + (size_t)row * CD + tid * 4);

    float s  = v.x + v.y + v.z + v.w;
    float s2 = v.x*v.x + v.y*v.y + v.z*v.z + v.w*v.w;
    #pragma unroll
    for (int o = 16; o; o >>= 1) {
        s  += __shfl_xor_sync(~0u, s,  o);
        s2 += __shfl_xor_sync(~0u, s2, o);
    }
    if ((tid & 31) == 0) { red[(tid >> 5)*2] = s; red[(tid >> 5)*2 + 1] = s2; }
    __syncthreads();
    if (tid == 0) {
        float a = 0.f, b2 = 0.f;
        #pragma unroll
        for (int w = 0; w < 8; w++) { a += red[w*2]; b2 += red[w*2 + 1]; }
        float mu  = a * (1.f / CD);
        float var = b2 * (1.f / CD) - mu * mu;
        bc[0] = mu; bc[1] = rsqrtf(var + 1e-5f);
    }
    __syncthreads();
    float mu = bc[0], rstd = bc[1];
    __syncthreads();

    const float4 g4 = *(const float4*)(ga + tid * 4);
    const float4 b4 = *(const float4*)(ba + tid * 4);
    float y[4];
    y[0] = (v.x - mu) * rstd * g4.x + b4.x;
    y[1] = (v.y - mu) * rstd * g4.y + b4.y;
    y[2] = (v.z - mu) * rstd * g4.z + b4.z;
    y[3] = (v.w - mu) * rstd * g4.w + b4.w;

    s  = y[0] + y[1] + y[2] + y[3];
    s2 = y[0]*y[0] + y[1]*y[1] + y[2]*y[2] + y[3]*y[3];
    #pragma unroll
    for (int o = 16; o; o >>= 1) {
        s  += __shfl_xor_sync(~0u, s,  o);
        s2 += __shfl_xor_sync(~0u, s2, o);
    }
    if ((tid & 31) == 0) { red[(tid >> 5)*2] = s; red[(tid >> 5)*2 + 1] = s2; }
    __syncthreads();
    if (tid == 0) {
        float a = 0.f, b2 = 0.f;
        #pragma unroll
        for (int w = 0; w < 8; w++) { a += red[w*2]; b2 += red[w*2 + 1]; }
        float mu2  = a * (1.f / CD);
        float var2 = b2 * (1.f / CD) - mu2 * mu2;
        bc[0] = mu2; bc[1] = rsqrtf(var2 + 1e-5f);
    }
    __syncthreads();
    mu = bc[0]; rstd = bc[1];

    const float4 g24 = *(const float4*)(gb + tid * 4);
    const float4 b24 = *(const float4*)(bb + tid * 4);
    float o0 = (y[0] - mu) * rstd * g24.x + b24.x;
    float o1 = (y[1] - mu) * rstd * g24.y + b24.y;
    float o2 = (y[2] - mu) * rstd * g24.z + b24.z;
    float o3 = (y[3] - mu) * rstd * g24.w + b24.w;
    __half* op = out + (size_t)row * CD + tid * 4;
    *(__half2*)(op)     = __floats2half2_rn(o0, o1);
    *(__half2*)(op + 2) = __floats2half2_rn(o2, o3);
}

__global__ __launch_bounds__(256) void ln1_kernel(
    const float* __restrict__ x,
    const float* __restrict__ g, const float* __restrict__ b,
    __half* __restrict__ out)
{
    __shared__ float red[16];
    __shared__ float bc[2];
    const int row = blockIdx.x, tid = threadIdx.x;
    const float4 v = *(const float4*)(x + (size_t)row * CD + tid * 4);

    float s  = v.x + v.y + v.z + v.w;
    float s2 = v.x*v.x + v.y*v.y + v.z*v.z + v.w*v.w;
    #pragma unroll
    for (int o = 16; o; o >>= 1) {
        s  += __shfl_xor_sync(~0u, s,  o);
        s2 += __shfl_xor_sync(~0u, s2, o);
    }
    if ((tid & 31) == 0) { red[(tid >> 5)*2] = s; red[(tid >> 5)*2 + 1] = s2; }
    __syncthreads();
    if (tid == 0) {
        float a = 0.f, b2 = 0.f;
        #pragma unroll
        for (int w = 0; w < 8; w++) { a += red[w*2]; b2 += red[w*2 + 1]; }
        float mu  = a * (1.f / CD);
        float var = b2 * (1.f / CD) - mu * mu;
        bc[0] = mu; bc[1] = rsqrtf(var + 1e-5f);
    }
    __syncthreads();
    const float mu = bc[0], rstd = bc[1];
    const float4 g4 = *(const float4*)(g + tid * 4);
    const float4 b4 = *(const float4*)(b + tid * 4);
    float o0 = (v.x - mu) * rstd * g4.x + b4.x;
    float o1 = (v.y - mu) * rstd * g4.y + b4.y;
    float o2 = (v.z - mu) * rstd * g4.z + b4.z;
    float o3 = (v.w - mu) * rstd * g4.w + b4.w;
    __half* op = out + (size_t)row * CD + tid * 4;
    *(__half2*)(op)     = __floats2half2_rn(o0, o1);
    *(__half2*)(op + 2) = __floats2half2_rn(o2, o3);
}

// ---------------------------------------------------------------------------
// FP16 tensor-core GEMM with ldmatrix A-fragments (unchanged)
// ---------------------------------------------------------------------------
__global__ __launch_bounds__(256, 2) void gemm_h(
    const __half* __restrict__ A,
    const __half2* __restrict__ Wp0, const __half2* __restrict__ Wp1,
    const __half2* __restrict__ Wp2,
    const float* __restrict__ b0, const float* __restrict__ b1,
    const float* __restrict__ b2,
    const float* __restrict__ res,
    float* __restrict__ C0, float* __restrict__ C1, float* __restrict__ C2,
    __half* __restrict__ H0, __half* __restrict__ H1, __half* __restrict__ H2,
    int vtz2, int M, int N, int K, int act)
{
    __shared__ uint32_t As[2][128 * 20];
    __shared__ uint32_t Bs[2][16 * 128];

    const int z = blockIdx.z;
    const __half2* Wp  = (z == 0) ? Wp0 : (z == 1) ? Wp1 : Wp2;
    const float*  bias = (z == 0) ? b0  : (z == 1) ? b1  : b2;
    float*        Cc   = (z == 0) ? C0  : (z == 1) ? C1  : C2;
    __half*       Hh   = (z == 0) ? H0  : (z == 1) ? H1  : H2;
    const bool    vt   = (z == 2) && vtz2;

    const int tid  = threadIdx.x;
    const int lane = tid & 31;
    const int warp = tid >> 5;
    const int wm = warp & 1;
    const int wn = warp >> 1;
    const int bm = blockIdx.y * 128;
    const int bn = blockIdx.x * 128;

    const int ar1 = tid >> 2,          aq1 = tid & 3;
    const int ar2 = (tid + 256) >> 2,  aq2 = (tid + 256) & 3;
    const int bk1 = tid >> 5,          bn1 = tid & 31;
    const int bk2 = (tid + 256) >> 5,  bn2 = (tid + 256) & 31;

    const uint32_t sA = (uint32_t)__cvta_generic_to_shared(&As[0][0]);
    const uint32_t sB = (uint32_t)__cvta_generic_to_shared(&Bs[0][0]);
    const uint32_t aD1 = sA + (uint32_t)(ar1 * 20 + aq1 * 4) * 4u;
    const uint32_t aD2 = sA + (uint32_t)(ar2 * 20 + aq2 * 4) * 4u;
    const uint32_t bD1 = sB + (uint32_t)(bk1 * 128 + ((bn1 * 4) ^ (8 * bk1))) * 4u;
    const uint32_t bD2 = sB + (uint32_t)(bk2 * 128 + ((bn2 * 4) ^ (8 * bk2))) * 4u;

    const __half*  gA1 = A + (size_t)(bm + ar1) * K + aq1 * 8;
    const __half*  gA2 = A + (size_t)(bm + ar2) * K + aq2 * 8;
    const __half2* gB1 = Wp + (size_t)bk1 * N + bn + bn1 * 4;
    const __half2* gB2 = Wp + (size_t)bk2 * N + bn + bn2 * 4;
    const size_t bStep = (size_t)16 * N;

    const int mi = lane >> 3;
    const int rr = lane & 7;
    uint32_t aL[4];
    #pragma unroll
    for (int mf = 0; mf < 4; mf++) {
        const int m = wm * 64 + mf * 16 + (mi & 1) * 8 + rr;
        aL[mf] = sA + (uint32_t)(m * 20 + (mi >> 1) * 4) * 4u;
    }

    float acc[4][4][4];
    #pragma unroll
    for (int i = 0; i < 4; i++)
        #pragma unroll
        for (int j = 0; j < 4; j++)
            #pragma unroll
            for (int r = 0; r < 4; r++) acc[i][j][r] = 0.f;

    auto issue = [&](uint32_t so) {
        cp16(aD1 + so * 10240u, gA1);
        cp16(aD2 + so * 10240u, gA2);
        cp16(bD1 + so * 8192u,  gB1);
        cp16(bD2 + so * 8192u,  gB2);
        gA1 += 32; gA2 += 32; gB1 += bStep; gB2 += bStep;
    };

    issue(0); cp_commit();
    issue(1); cp_commit();

    const int nK = K >> 5;
    const int r4 = lane >> 2;
    const int c4 = lane & 3;
    const int nb0 = wn * 32 + r4;

    for (int kt = 0; kt < nK; kt++) {
        cp_wait<1>();
        __syncthreads();
        const int cur = kt & 1;
        const uint32_t curA = (uint32_t)cur * 10240u;
        const uint32_t* Bp = &Bs[cur][0];

        #pragma unroll
        for (int p = 0; p < 2; p++) {
            uint32_t af[4][4], bf[4][2];
            #pragma unroll
            for (int mf = 0; mf < 4; mf++)
                ldsm4(af[mf], aL[mf] + curA + (uint32_t)(p * 32));
            #pragma unroll
            for (int nf = 0; nf < 4; nf++) {
                const int n = nb0 + nf * 8;
                bf[nf][0] = Bp[(p * 8 + c4) * 128     + (n ^ (64 * p + 8 * c4))];
                bf[nf][1] = Bp[(p * 8 + c4 + 4) * 128 + (n ^ (64 * p + 8 * c4 + 32))];
            }
            #pragma unroll
            for (int mf = 0; mf < 4; mf++)
                #pragma unroll
                for (int nf = 0; nf < 4; nf++)
                    mma_f16(acc[mf][nf], af[mf], bf[nf]);
        }
        __syncthreads();
        if (kt + 2 < nK) issue(cur);
        cp_commit();
    }

    #pragma unroll
    for (int mf = 0; mf < 4; mf++) {
        #pragma unroll
        for (int nf = 0; nf < 4; nf++) {
            const int col = bn + wn * 32 + nf * 8 + c4 * 2;
            const float bx = bias[col], by = bias[col + 1];
            #pragma unroll
            for (int h = 0; h < 2; h++) {
                const int row = bm + wm * 64 + mf * 16 + r4 + h * 8;
                float ox = acc[mf][nf][h * 2 + 0] + bx;
                float oy = acc[mf][nf][h * 2 + 1] + by;
                if (act) {
                    ox *= 1.f / (1.f + __expf(-ox));
                    oy *= 1.f / (1.f + __expf(-oy));
                }
                const size_t off = (size_t)row * N + col;
                if (res) {
                    const float2 rr2 = *(const float2*)(res + off);
                    ox += rr2.x; oy += rr2.y;
                }
                if (Cc) {
                    float2 o; o.x = ox; o.y = oy;
                    *(float2*)(Cc + off) = o;
                }
                if (Hh) {
                    if (vt) {
                        Hh[(size_t)col * M + row]       = __float2half(ox);
                        Hh[(size_t)(col + 1) * M + row] = __float2half(oy);
                    } else {
                        *(__half2*)(Hh + off) = __floats2half2_rn(ox, oy);
                    }
                }
            }
        }
    }
}

// ---------------------------------------------------------------------------
// FP16 flash attention v2 (FIXED): 128-row Q tile, 256 threads,
// GLOBAL-frame causal comparisons (grow = q0 + wrow).
// ---------------------------------------------------------------------------
#define AST 36
#define ATTN_SMEM ((128*AST + 2*64*AST + 2*64*AST + 8*16*AST) * 4)  // 73728 B

__global__ __launch_bounds__(256, 2) void attn_h(
    const __half* __restrict__ Qh, const __half* __restrict__ Kh,
    const __half* __restrict__ Vt, __half* __restrict__ O)
{
    extern __shared__ uint32_t sm[];
    uint32_t* Qs = sm;                    // [128][36]
    uint32_t* Ks = Qs + 128 * AST;        // [2][64][36]
    uint32_t* Vs = Ks + 2 * 64 * AST;     // [2][64][36]
    uint32_t* Ps = Vs + 2 * 64 * AST;     // [8][16][36]

    const int bh = blockIdx.y;
    const int b = bh >> 4, h = bh & 15;
    const int qt = blockIdx.x;
    const int q0 = qt * 128;
    const int tid = threadIdx.x;
    const int lane = tid & 31;
    const int warp = tid >> 5;
    const int r4 = lane >> 2;
    const int c4 = lane & 3;

    const __half* qg = Qh + (size_t)(b * TD + q0) * CD + h * HD;
    const __half* kg = Kh + (size_t)b * TD * CD + h * HD;
    const __half* vg = Vt + (size_t)(h * HD) * NT + b * TD;

    const uint32_t sQ = (uint32_t)__cvta_generic_to_shared(Qs);
    const uint32_t sK = (uint32_t)__cvta_generic_to_shared(Ks);
    const uint32_t sV = (uint32_t)__cvta_generic_to_shared(Vs);

    #pragma unroll
    for (int i = 0; i < 4; i++) {
        const int idx = tid + i * 256;
        const int row = idx >> 3, cc = idx & 7;
        cp16(sQ + (uint32_t)(row * AST + cc * 4) * 4u, qg + row * CD + cc * 8);
    }
    auto issue_kv = [&](int buf, int k0) {
        #pragma unroll
        for (int i = 0; i < 2; i++) {
            const int idx = tid + i * 256;
            const int row = idx >> 3, cc = idx & 7;
            cp16(sK + (uint32_t)(buf * 64 * AST + row * AST + cc * 4) * 4u,
                 kg + (size_t)(k0 + row) * CD + cc * 8);
            cp16(sV + (uint32_t)(buf * 64 * AST + row * AST + cc * 4) * 4u,
                 vg + (size_t)row * NT + k0 + cc * 8);
        }
    };
    const int nkt = 2 * qt + 2;    // key tiles covering [0, q0+128)
    issue_kv(0, 0);
    cp_commit();
    if (nkt > 1) { issue_kv(1, 64); cp_commit(); }

    uint32_t qf[4][4];
    float oacc[8][4];
    #pragma unroll
    for (int nt = 0; nt < 8; nt++)
        #pragma unroll
        for (int r = 0; r < 4; r++) oacc[nt][r] = 0.f;
    float m0 = -1e30f, m1 = -1e30f, l0 = 0.f, l1 = 0.f;

    uint32_t* Pw = Ps + warp * 16 * AST;
    const __half2 sc = __float2half2_rn(0.125f * 1.4426950408889634f);
    const int wrow = warp * 16;          // tile-local first row
    const int grow = q0 + wrow;          // GLOBAL first row of this warp

    for (int kt = 0; kt < nkt; kt++) {
        if (kt + 1 < nkt) cp_wait<1>(); else cp_wait<0>();
        __syncthreads();
        const int cur = kt & 1;
        const int k0 = kt * 64;          // global key offset of this tile
        const uint32_t* Kp = Ks + cur * 64 * AST;
        const uint32_t* Vp = Vs + cur * 64 * AST;

        if (kt == 0) {
            const uint32_t* qp = Qs + (wrow + r4) * AST;
            #pragma unroll
            for (int p = 0; p < 4; p++) {
                qf[p][0] = h2scale(qp[p * 8 + c4], sc);
                qf[p][1] = h2scale(qp[8 * AST + p * 8 + c4], sc);
                qf[p][2] = h2scale(qp[p * 8 + c4 + 4], sc);
                qf[p][3] = h2scale(qp[8 * AST + p * 8 + c4 + 4], sc);
            }
        }

        // skip tiles entirely in this warp's causal future (GLOBAL frame)
        if (k0 <= grow + 15) {
            float sacc[8][4];
            #pragma unroll
            for (int nt = 0; nt < 8; nt++)
                #pragma unroll
                for (int r = 0; r < 4; r++) sacc[nt][r] = 0.f;

            #pragma unroll
            for (int p = 0; p < 4; p++) {
                #pragma unroll
                for (int nt = 0; nt < 8; nt++) {
                    const uint32_t* kp = Kp + (nt * 8 + r4) * AST + p * 8;
                    uint32_t bf[2];
                    bf[0] = kp[c4];
                    bf[1] = kp[c4 + 4];
                    mma_f16(sacc[nt], qf[p], bf);
                }
            }

            // causal mask when the tile crosses this warp's diagonal (GLOBAL)
            if (k0 + 63 > grow) {
                const int row0 = grow + r4;
                #pragma unroll
                for (int nt = 0; nt < 8; nt++) {
                    const int cb = k0 + nt * 8 + 2 * c4;
                    if (cb + 0 > row0)     sacc[nt][0] = -1e30f;
                    if (cb + 1 > row0)     sacc[nt][1] = -1e30f;
                    if (cb + 0 > row0 + 8) sacc[nt][2] = -1e30f;
                    if (cb + 1 > row0 + 8) sacc[nt][3] = -1e30f;
                }
            }

            float rm0 = -1e30f, rm1 = -1e30f;
            #pragma unroll
            for (int nt = 0; nt < 8; nt++) {
                rm0 = fmaxf(rm0, fmaxf(sacc[nt][0], sacc[nt][1]));
                rm1 = fmaxf(rm1, fmaxf(sacc[nt][2], sacc[nt][3]));
            }
            rm0 = fmaxf(rm0, __shfl_xor_sync(~0u, rm0, 1));
            rm0 = fmaxf(rm0, __shfl_xor_sync(~0u, rm0, 2));
            rm1 = fmaxf(rm1, __shfl_xor_sync(~0u, rm1, 1));
            rm1 = fmaxf(rm1, __shfl_xor_sync(~0u, rm1, 2));

            const float mn0 = fmaxf(m0, rm0), mn1 = fmaxf(m1, rm1);
            const float f0 = exp2f(m0 - mn0), f1 = exp2f(m1 - mn1);
            m0 = mn0; m1 = mn1;

            float rs0 = 0.f, rs1 = 0.f;
            #pragma unroll
            for (int nt = 0; nt < 8; nt++) {
                float p0 = exp2f(sacc[nt][0] - mn0);
                float p1 = exp2f(sacc[nt][1] - mn0);
                float p2 = exp2f(sacc[nt][2] - mn1);
                float p3 = exp2f(sacc[nt][3] - mn1);
                rs0 += p0 + p1; rs1 += p2 + p3;
                __half2 w0 = __floats2half2_rn(p0, p1);
                __half2 w1 = __floats2half2_rn(p2, p3);
                Pw[r4 * AST + nt * 4 + c4]       = *(uint32_t*)&w0;
                Pw[(r4 + 8) * AST + nt * 4 + c4] = *(uint32_t*)&w1;
            }
            rs0 += __shfl_xor_sync(~0u, rs0, 1);
            rs0 += __shfl_xor_sync(~0u, rs0, 2);
            rs1 += __shfl_xor_sync(~0u, rs1, 1);
            rs1 += __shfl_xor_sync(~0u, rs1, 2);
            l0 = l0 * f0 + rs0;
            l1 = l1 * f1 + rs1;

            #pragma unroll
            for (int nt = 0; nt < 8; nt++) {
                oacc[nt][0] *= f0; oacc[nt][1] *= f0;
                oacc[nt][2] *= f1; oacc[nt][3] *= f1;
            }
            __syncwarp();

            #pragma unroll
            for (int p = 0; p < 4; p++) {
                uint32_t af[4];
                const uint32_t* pp  = Pw + r4 * AST + p * 8;
                const uint32_t* pp8 = Pw + (r4 + 8) * AST + p * 8;
                af[0] = pp[c4];
                af[1] = pp8[c4];
                af[2] = pp[c4 + 4];
                af[3] = pp8[c4 + 4];
                #pragma unroll
                for (int nt = 0; nt < 8; nt++) {
                    const uint32_t* vp = Vp + (nt * 8 + r4) * AST + p * 8;
                    uint32_t bf[2];
                    bf[0] = vp[c4];
                    bf[1] = vp[c4 + 4];
                    mma_f16(oacc[nt], af, bf);
                }
            }
        }

        __syncthreads();
        if (kt + 2 < nkt) { issue_kv(cur, (kt + 2) * 64); cp_commit(); }
    }

    const float inv0 = 1.f / l0, inv1 = 1.f / l1;
    const int row0 = grow + r4;
    #pragma unroll
    for (int nt = 0; nt < 8; nt++) {
        const int col = h * HD + nt * 8 + 2 * c4;
        *(__half2*)(O + (size_t)(b * TD + row0) * CD + col) =
            __floats2half2_rn(oacc[nt][0] * inv0, oacc[nt][1] * inv0);
        *(__half2*)(O + (size_t)(b * TD + row0 + 8) * CD + col) =
            __floats2half2_rn(oacc[nt][2] * inv1, oacc[nt][3] * inv1);
    }
}

// ---------------------------------------------------------------------------
// Launch
// ---------------------------------------------------------------------------
extern "C" void kernel_launch(void* const* d_in, const int* in_sizes, int n_in,
                              void* d_out, int out_size)
{
    const float* x      = (const float*)d_in[0];
    const float* ln_a_g = (const float*)d_in[1];
    const float* ln_a_b = (const float*)d_in[2];
    const float* ln_b_g = (const float*)d_in[3];
    const float* ln_b_b = (const float*)d_in[4];
    const float* ln_c_g = (const float*)d_in[5];
    const float* ln_c_b = (const float*)d_in[6];
    const float* Wq = (const float*)d_in[7];  const float* bq = (const float*)d_in[8];
    const float* Wk = (const float*)d_in[9];  const float* bk = (const float*)d_in[10];
    const float* Wv = (const float*)d_in[11]; const float* bv = (const float*)d_in[12];
    const float* Wo = (const float*)d_in[13]; const float* bo = (const float*)d_in[14];
    const float* We = (const float*)d_in[15]; const float* be = (const float*)d_in[16];
    const float* Wd = (const float*)d_in[17]; const float* bd = (const float*)d_in[18];
    float* out = (float*)d_out;

    float *x2;
    __half *th, *t2h, *qh, *kh, *vt, *ctxh, *hh;
    __half2 *wqp, *wkp, *wvp, *wop, *wep, *wdp;
    cudaGetSymbolAddress((void**)&x2,   g_x2);
    cudaGetSymbolAddress((void**)&th,   g_th);
    cudaGetSymbolAddress((void**)&t2h,  g_t2h);
    cudaGetSymbolAddress((void**)&qh,   g_qh);
    cudaGetSymbolAddress((void**)&kh,   g_kh);
    cudaGetSymbolAddress((void**)&vt,   g_vt);
    cudaGetSymbolAddress((void**)&ctxh, g_ctxh);
    cudaGetSymbolAddress((void**)&hh,   g_hh);
    cudaGetSymbolAddress((void**)&wqp,  g_wqp);
    cudaGetSymbolAddress((void**)&wkp,  g_wkp);
    cudaGetSymbolAddress((void**)&wvp,  g_wvp);
    cudaGetSymbolAddress((void**)&wop,  g_wop);
    cudaGetSymbolAddress((void**)&wep,  g_wep);
    cudaGetSymbolAddress((void**)&wdp,  g_wdp);

    cudaFuncSetAttribute(attn_h, cudaFuncAttributeMaxDynamicSharedMemorySize,
                         ATTN_SMEM);
    cudaFuncSetAttribute(attn_h, cudaFuncAttributePreferredSharedMemoryCarveout,
                         100);

    // 0. fused weight conversion
    {
        const int total = 3 * (1 << 21);
        wconv_all<<<total / 256, 256>>>(Wq, Wk, Wv, Wo, We, Wd,
                                        wqp, wkp, wvp, wop, wep, wdp);
    }

    // 1. th = fp16(LN_b(LN_a(x)))
    ln2_kernel<<<NT, 256>>>(x, ln_a_g, ln_a_b, ln_b_g, ln_b_b, th);

    // 2. QKV (fused): q,k fp16 row-major; v fp16 transposed
    {
        dim3 grid(CD / 128, NT / 128, 3);
        gemm_h<<<grid, 256>>>(th, wqp, wkp, wvp, bq, bk, bv, nullptr,
                              nullptr, nullptr, nullptr,
                              qh, kh, vt, 1, NT, CD, CD, 0);
    }

    // 3. causal attention (fp16, 128-row tiles) -> ctxh
    {
        dim3 grid(TD / 128, BD * HN);
        attn_h<<<grid, 256, ATTN_SMEM>>>(qh, kh, vt, ctxh);
    }

    // 4. x2 = x + ctx @ Wo + bo
    {
        dim3 grid(CD / 128, NT / 128, 1);
        gemm_h<<<grid, 256>>>(ctxh, wop, wop, wop, bo, bo, bo, x,
                              x2, x2, x2, nullptr, nullptr, nullptr,
                              0, NT, CD, CD, 0);
    }

    // 5. t2h = fp16(LN_c(x2))
    ln1_kernel<<<NT, 256>>>(x2, ln_c_g, ln_c_b, t2h);

    // 6. hh = fp16(silu(t2 @ We + be))
    {
        dim3 grid(DFFD / 128, NT / 128, 1);
        gemm_h<<<grid, 256>>>(t2h, wep, wep, wep, be, be, be, nullptr,
                              nullptr, nullptr, nullptr, hh, hh, hh,
                              0, NT, DFFD, CD, 1);
    }

    // 7. out = x2 + h @ Wd + bd
    {
        dim3 grid(CD / 128, NT / 128, 1);
        gemm_h<<<grid, 256>>>(hh, wdp, wdp, wdp, bd, bd, bd, x2,
                              out, out, out, nullptr, nullptr, nullptr,
                              0, NT, CD, DFFD, 0);
    }
}

// round 13
// speedup vs baseline: 1.0191x; 1.0191x over previous
#include <cuda_runtime.h>
#include <cuda_fp16.h>
#include <math.h>
#include <stdint.h>

// Problem dims
#define BD   2
#define TD   2048
#define CD   1024
#define HN   16
#define HD   64
#define DFFD 4096
#define NT   (BD * TD)   // 4096 tokens

// ---------------------------------------------------------------------------
// Scratch (device globals)
// ---------------------------------------------------------------------------
__device__ float  g_x2 [(size_t)NT * CD];
__device__ __half g_th  [(size_t)NT * CD];
__device__ __half g_t2h [(size_t)NT * CD];
__device__ __half g_qh  [(size_t)NT * CD];
__device__ __half g_kh  [(size_t)NT * CD];
__device__ __half g_vt  [(size_t)CD * NT];    // V transposed [dim][token]
__device__ __half g_ctxh[(size_t)NT * CD];
__device__ __half g_hh  [(size_t)NT * DFFD];
// k-pair-packed fp16 weights
__device__ __half2 g_wqp[(CD/2) * CD];
__device__ __half2 g_wkp[(CD/2) * CD];
__device__ __half2 g_wvp[(CD/2) * CD];
__device__ __half2 g_wop[(CD/2) * CD];
__device__ __half2 g_wep[(CD/2) * DFFD];
__device__ __half2 g_wdp[(DFFD/2) * CD];

// ---------------------------------------------------------------------------
// Helpers
// ---------------------------------------------------------------------------
__device__ __forceinline__ void cp16(uint32_t smem_dst, const void* gptr) {
    asm volatile("cp.async.cg.shared.global [%0], [%1], 16;\n"
                 :: "r"(smem_dst), "l"(gptr));
}
__device__ __forceinline__ void cp_commit() {
    asm volatile("cp.async.commit_group;\n" ::: "memory");
}
template <int N>
__device__ __forceinline__ void cp_wait() {
    asm volatile("cp.async.wait_group %0;\n" :: "n"(N) : "memory");
}
__device__ __forceinline__ void mma_f16(float* c, const uint32_t* a, const uint32_t* b) {
    asm volatile(
        "mma.sync.aligned.m16n8k16.row.col.f32.f16.f16.f32 "
        "{%0,%1,%2,%3},{%4,%5,%6,%7},{%8,%9},{%0,%1,%2,%3};"
        : "+f"(c[0]), "+f"(c[1]), "+f"(c[2]), "+f"(c[3])
        : "r"(a[0]), "r"(a[1]), "r"(a[2]), "r"(a[3]), "r"(b[0]), "r"(b[1]));
}
__device__ __forceinline__ void ldsm4(uint32_t* r, uint32_t addr) {
    asm volatile(
        "ldmatrix.sync.aligned.m8n8.x4.shared.b16 {%0,%1,%2,%3}, [%4];"
        : "=r"(r[0]), "=r"(r[1]), "=r"(r[2]), "=r"(r[3]) : "r"(addr));
}
__device__ __forceinline__ uint32_t h2scale(uint32_t w, __half2 s) {
    __half2 a = *(__half2*)&w;
    a = __hmul2(a, s);
    return *(uint32_t*)&a;
}

// ---------------------------------------------------------------------------
// Fused weight conversion (one launch)
// ---------------------------------------------------------------------------
__global__ __launch_bounds__(256) void wconv_all(
    const float* __restrict__ Wq, const float* __restrict__ Wk,
    const float* __restrict__ Wv, const float* __restrict__ Wo,
    const float* __restrict__ We, const float* __restrict__ Wd,
    __half2* __restrict__ oq, __half2* __restrict__ ok,
    __half2* __restrict__ ov, __half2* __restrict__ oo,
    __half2* __restrict__ oe, __half2* __restrict__ od)
{
    int idx = blockIdx.x * 256 + threadIdx.x;
    const float* W;
    __half2* out;
    int nshift, i;
    if (idx < (1 << 21)) {
        const int m = idx >> 19;
        i = idx & ((1 << 19) - 1);
        W   = (m == 0) ? Wq : (m == 1) ? Wk : (m == 2) ? Wv : Wo;
        out = (m == 0) ? oq : (m == 1) ? ok : (m == 2) ? ov : oo;
        nshift = 10;
    } else if (idx < (2 << 21)) {
        i = idx - (1 << 21);
        W = We; out = oe; nshift = 12;
    } else {
        i = idx - (2 << 21);
        W = Wd; out = od; nshift = 10;
    }
    const int kk = i >> nshift;
    const int n  = i & ((1 << nshift) - 1);
    const size_t base = ((size_t)(2 * kk) << nshift) + n;
    out[i] = __floats2half2_rn(W[base], W[base + ((size_t)1 << nshift)]);
}

// ---------------------------------------------------------------------------
// Fused double LayerNorm -> fp16 out
// ---------------------------------------------------------------------------
__global__ __launch_bounds__(256) void ln2_kernel(
    const float* __restrict__ x,
    const float* __restrict__ ga, const float* __restrict__ ba,
    const float* __restrict__ gb, const float* __restrict__ bb,
    __half* __restrict__ out)
{
    __shared__ float red[16];
    __shared__ float bc[2];
    const int row = blockIdx.x, tid = threadIdx.x;
    const float4 v = *(const float4*)(x + (size_t)row * CD + tid * 4);

    float s  = v.x + v.y + v.z + v.w;
    float s2 = v.x*v.x + v.y*v.y + v.z*v.z + v.w*v.w;
    #pragma unroll
    for (int o = 16; o; o >>= 1) {
        s  += __shfl_xor_sync(~0u, s,  o);
        s2 += __shfl_xor_sync(~0u, s2, o);
    }
    if ((tid & 31) == 0) { red[(tid >> 5)*2] = s; red[(tid >> 5)*2 + 1] = s2; }
    __syncthreads();
    if (tid == 0) {
        float a = 0.f, b2 = 0.f;
        #pragma unroll
        for (int w = 0; w < 8; w++) { a += red[w*2]; b2 += red[w*2 + 1]; }
        float mu  = a * (1.f / CD);
        float var = b2 * (1.f / CD) - mu * mu;
        bc[0] = mu; bc[1] = rsqrtf(var + 1e-5f);
    }
    __syncthreads();
    float mu = bc[0], rstd = bc[1];
    __syncthreads();

    const float4 g4 = *(const float4*)(ga + tid * 4);
    const float4 b4 = *(const float4*)(ba + tid * 4);
    float y[4];
    y[0] = (v.x - mu) * rstd * g4.x + b4.x;
    y[1] = (v.y - mu) * rstd * g4.y + b4.y;
    y[2] = (v.z - mu) * rstd * g4.z + b4.z;
    y[3] = (v.w - mu) * rstd * g4.w + b4.w;

    s  = y[0] + y[1] + y[2] + y[3];
    s2 = y[0]*y[0] + y[1]*y[1] + y[2]*y[2] + y[3]*y[3];
    #pragma unroll
    for (int o = 16; o; o >>= 1) {
        s  += __shfl_xor_sync(~0u, s,  o);
        s2 += __shfl_xor_sync(~0u, s2, o);
    }
    if ((tid & 31) == 0) { red[(tid >> 5)*2] = s; red[(tid >> 5)*2 + 1] = s2; }
    __syncthreads();
    if (tid == 0) {
        float a = 0.f, b2 = 0.f;
        #pragma unroll
        for (int w = 0; w < 8; w++) { a += red[w*2]; b2 += red[w*2 + 1]; }
        float mu2  = a * (1.f / CD);
        float var2 = b2 * (1.f / CD) - mu2 * mu2;
        bc[0] = mu2; bc[1] = rsqrtf(var2 + 1e-5f);
    }
    __syncthreads();
    mu = bc[0]; rstd = bc[1];

    const float4 g24 = *(const float4*)(gb + tid * 4);
    const float4 b24 = *(const float4*)(bb + tid * 4);
    float o0 = (y[0] - mu) * rstd * g24.x + b24.x;
    float o1 = (y[1] - mu) * rstd * g24.y + b24.y;
    float o2 = (y[2] - mu) * rstd * g24.z + b24.z;
    float o3 = (y[3] - mu) * rstd * g24.w + b24.w;
    __half* op = out + (size_t)row * CD + tid * 4;
    *(__half2*)(op)     = __floats2half2_rn(o0, o1);
    *(__half2*)(op + 2) = __floats2half2_rn(o2, o3);
}

__global__ __launch_bounds__(256) void ln1_kernel(
    const float* __restrict__ x,
    const float* __restrict__ g, const float* __restrict__ b,
    __half* __restrict__ out)
{
    __shared__ float red[16];
    __shared__ float bc[2];
    const int row = blockIdx.x, tid = threadIdx.x;
    const float4 v = *(const float4*)(x + (size_t)row * CD + tid * 4);

    float s  = v.x + v.y + v.z + v.w;
    float s2 = v.x*v.x + v.y*v.y + v.z*v.z + v.w*v.w;
    #pragma unroll
    for (int o = 16; o; o >>= 1) {
        s  += __shfl_xor_sync(~0u, s,  o);
        s2 += __shfl_xor_sync(~0u, s2, o);
    }
    if ((tid & 31) == 0) { red[(tid >> 5)*2] = s; red[(tid >> 5)*2 + 1] = s2; }
    __syncthreads();
    if (tid == 0) {
        float a = 0.f, b2 = 0.f;
        #pragma unroll
        for (int w = 0; w < 8; w++) { a += red[w*2]; b2 += red[w*2 + 1]; }
        float mu  = a * (1.f / CD);
        float var = b2 * (1.f / CD) - mu * mu;
        bc[0] = mu; bc[1] = rsqrtf(var + 1e-5f);
    }
    __syncthreads();
    const float mu = bc[0], rstd = bc[1];
    const float4 g4 = *(const float4*)(g + tid * 4);
    const float4 b4 = *(const float4*)(b + tid * 4);
    float o0 = (v.x - mu) * rstd * g4.x + b4.x;
    float o1 = (v.y - mu) * rstd * g4.y + b4.y;
    float o2 = (v.z - mu) * rstd * g4.z + b4.z;
    float o3 = (v.w - mu) * rstd * g4.w + b4.w;
    __half* op = out + (size_t)row * CD + tid * 4;
    *(__half2*)(op)     = __floats2half2_rn(o0, o1);
    *(__half2*)(op + 2) = __floats2half2_rn(o2, o3);
}

// ---------------------------------------------------------------------------
// FP16 tensor-core GEMM with ldmatrix A-fragments (unchanged)
// ---------------------------------------------------------------------------
__global__ __launch_bounds__(256, 2) void gemm_h(
    const __half* __restrict__ A,
    const __half2* __restrict__ Wp0, const __half2* __restrict__ Wp1,
    const __half2* __restrict__ Wp2,
    const float* __restrict__ b0, const float* __restrict__ b1,
    const float* __restrict__ b2,
    const float* __restrict__ res,
    float* __restrict__ C0, float* __restrict__ C1, float* __restrict__ C2,
    __half* __restrict__ H0, __half* __restrict__ H1, __half* __restrict__ H2,
    int vtz2, int M, int N, int K, int act)
{
    __shared__ uint32_t As[2][128 * 20];
    __shared__ uint32_t Bs[2][16 * 128];

    const int z = blockIdx.z;
    const __half2* Wp  = (z == 0) ? Wp0 : (z == 1) ? Wp1 : Wp2;
    const float*  bias = (z == 0) ? b0  : (z == 1) ? b1  : b2;
    float*        Cc   = (z == 0) ? C0  : (z == 1) ? C1  : C2;
    __half*       Hh   = (z == 0) ? H0  : (z == 1) ? H1  : H2;
    const bool    vt   = (z == 2) && vtz2;

    const int tid  = threadIdx.x;
    const int lane = tid & 31;
    const int warp = tid >> 5;
    const int wm = warp & 1;
    const int wn = warp >> 1;
    const int bm = blockIdx.y * 128;
    const int bn = blockIdx.x * 128;

    const int ar1 = tid >> 2,          aq1 = tid & 3;
    const int ar2 = (tid + 256) >> 2,  aq2 = (tid + 256) & 3;
    const int bk1 = tid >> 5,          bn1 = tid & 31;
    const int bk2 = (tid + 256) >> 5,  bn2 = (tid + 256) & 31;

    const uint32_t sA = (uint32_t)__cvta_generic_to_shared(&As[0][0]);
    const uint32_t sB = (uint32_t)__cvta_generic_to_shared(&Bs[0][0]);
    const uint32_t aD1 = sA + (uint32_t)(ar1 * 20 + aq1 * 4) * 4u;
    const uint32_t aD2 = sA + (uint32_t)(ar2 * 20 + aq2 * 4) * 4u;
    const uint32_t bD1 = sB + (uint32_t)(bk1 * 128 + ((bn1 * 4) ^ (8 * bk1))) * 4u;
    const uint32_t bD2 = sB + (uint32_t)(bk2 * 128 + ((bn2 * 4) ^ (8 * bk2))) * 4u;

    const __half*  gA1 = A + (size_t)(bm + ar1) * K + aq1 * 8;
    const __half*  gA2 = A + (size_t)(bm + ar2) * K + aq2 * 8;
    const __half2* gB1 = Wp + (size_t)bk1 * N + bn + bn1 * 4;
    const __half2* gB2 = Wp + (size_t)bk2 * N + bn + bn2 * 4;
    const size_t bStep = (size_t)16 * N;

    const int mi = lane >> 3;
    const int rr = lane & 7;
    uint32_t aL[4];
    #pragma unroll
    for (int mf = 0; mf < 4; mf++) {
        const int m = wm * 64 + mf * 16 + (mi & 1) * 8 + rr;
        aL[mf] = sA + (uint32_t)(m * 20 + (mi >> 1) * 4) * 4u;
    }

    float acc[4][4][4];
    #pragma unroll
    for (int i = 0; i < 4; i++)
        #pragma unroll
        for (int j = 0; j < 4; j++)
            #pragma unroll
            for (int r = 0; r < 4; r++) acc[i][j][r] = 0.f;

    auto issue = [&](uint32_t so) {
        cp16(aD1 + so * 10240u, gA1);
        cp16(aD2 + so * 10240u, gA2);
        cp16(bD1 + so * 8192u,  gB1);
        cp16(bD2 + so * 8192u,  gB2);
        gA1 += 32; gA2 += 32; gB1 += bStep; gB2 += bStep;
    };

    issue(0); cp_commit();
    issue(1); cp_commit();

    const int nK = K >> 5;
    const int r4 = lane >> 2;
    const int c4 = lane & 3;
    const int nb0 = wn * 32 + r4;

    for (int kt = 0; kt < nK; kt++) {
        cp_wait<1>();
        __syncthreads();
        const int cur = kt & 1;
        const uint32_t curA = (uint32_t)cur * 10240u;
        const uint32_t* Bp = &Bs[cur][0];

        #pragma unroll
        for (int p = 0; p < 2; p++) {
            uint32_t af[4][4], bf[4][2];
            #pragma unroll
            for (int mf = 0; mf < 4; mf++)
                ldsm4(af[mf], aL[mf] + curA + (uint32_t)(p * 32));
            #pragma unroll
            for (int nf = 0; nf < 4; nf++) {
                const int n = nb0 + nf * 8;
                bf[nf][0] = Bp[(p * 8 + c4) * 128     + (n ^ (64 * p + 8 * c4))];
                bf[nf][1] = Bp[(p * 8 + c4 + 4) * 128 + (n ^ (64 * p + 8 * c4 + 32))];
            }
            #pragma unroll
            for (int mf = 0; mf < 4; mf++)
                #pragma unroll
                for (int nf = 0; nf < 4; nf++)
                    mma_f16(acc[mf][nf], af[mf], bf[nf]);
        }
        __syncthreads();
        if (kt + 2 < nK) issue(cur);
        cp_commit();
    }

    #pragma unroll
    for (int mf = 0; mf < 4; mf++) {
        #pragma unroll
        for (int nf = 0; nf < 4; nf++) {
            const int col = bn + wn * 32 + nf * 8 + c4 * 2;
            const float bx = bias[col], by = bias[col + 1];
            #pragma unroll
            for (int h = 0; h < 2; h++) {
                const int row = bm + wm * 64 + mf * 16 + r4 + h * 8;
                float ox = acc[mf][nf][h * 2 + 0] + bx;
                float oy = acc[mf][nf][h * 2 + 1] + by;
                if (act) {
                    ox *= 1.f / (1.f + __expf(-ox));
                    oy *= 1.f / (1.f + __expf(-oy));
                }
                const size_t off = (size_t)row * N + col;
                if (res) {
                    const float2 rr2 = *(const float2*)(res + off);
                    ox += rr2.x; oy += rr2.y;
                }
                if (Cc) {
                    float2 o; o.x = ox; o.y = oy;
                    *(float2*)(Cc + off) = o;
                }
                if (Hh) {
                    if (vt) {
                        Hh[(size_t)col * M + row]       = __float2half(ox);
                        Hh[(size_t)(col + 1) * M + row] = __float2half(oy);
                    } else {
                        *(__half2*)(Hh + off) = __floats2half2_rn(ox, oy);
                    }
                }
            }
        }
    }
}

// ---------------------------------------------------------------------------
// FP16 flash attention v3: 128-row Q tile, 256 threads, register-resident P,
// ldmatrix K/V fragments, exp2 softmax, global-frame causal.
// ---------------------------------------------------------------------------
#define AST 36
#define ATTN_SMEM ((128*AST + 2*64*AST + 2*64*AST) * 4)   // 55296 B

__global__ __launch_bounds__(256, 2) void attn_h(
    const __half* __restrict__ Qh, const __half* __restrict__ Kh,
    const __half* __restrict__ Vt, __half* __restrict__ O)
{
    extern __shared__ uint32_t sm[];
    uint32_t* Qs = sm;                    // [128][36]
    uint32_t* Ks = Qs + 128 * AST;        // [2][64][36]
    uint32_t* Vs = Ks + 2 * 64 * AST;     // [2][64][36]  ([dim][key-pair])

    const int bh = blockIdx.y;
    const int b = bh >> 4, h = bh & 15;
    const int qt = blockIdx.x;
    const int q0 = qt * 128;
    const int tid = threadIdx.x;
    const int lane = tid & 31;
    const int warp = tid >> 5;
    const int r4 = lane >> 2;
    const int c4 = lane & 3;

    const __half* qg = Qh + (size_t)(b * TD + q0) * CD + h * HD;
    const __half* kg = Kh + (size_t)b * TD * CD + h * HD;
    const __half* vg = Vt + (size_t)(h * HD) * NT + b * TD;

    const uint32_t sQ = (uint32_t)__cvta_generic_to_shared(Qs);
    const uint32_t sK = (uint32_t)__cvta_generic_to_shared(Ks);
    const uint32_t sV = (uint32_t)__cvta_generic_to_shared(Vs);

    // Q: 128 rows x 128 B
    #pragma unroll
    for (int i = 0; i < 4; i++) {
        const int idx = tid + i * 256;
        const int row = idx >> 3, cc = idx & 7;
        cp16(sQ + (uint32_t)(row * AST + cc * 4) * 4u, qg + row * CD + cc * 8);
    }
    auto issue_kv = [&](int buf, int k0) {
        #pragma unroll
        for (int i = 0; i < 2; i++) {
            const int idx = tid + i * 256;
            const int row = idx >> 3, cc = idx & 7;
            cp16(sK + (uint32_t)(buf * 64 * AST + row * AST + cc * 4) * 4u,
                 kg + (size_t)(k0 + row) * CD + cc * 8);
            cp16(sV + (uint32_t)(buf * 64 * AST + row * AST + cc * 4) * 4u,
                 vg + (size_t)row * NT + k0 + cc * 8);
        }
    };
    const int nkt = 2 * qt + 2;
    issue_kv(0, 0);
    cp_commit();
    if (nkt > 1) { issue_kv(1, 64); cp_commit(); }

    // ldmatrix per-thread base: row (lane&7) within 8-row block, matrix lane>>3
    const uint32_t lmOff = (uint32_t)((lane & 7) * AST + (lane >> 3) * 4) * 4u;

    uint32_t qf[4][4];
    float oacc[8][4];
    #pragma unroll
    for (int nt = 0; nt < 8; nt++)
        #pragma unroll
        for (int r = 0; r < 4; r++) oacc[nt][r] = 0.f;
    float m0 = -1e30f, m1 = -1e30f, l0 = 0.f, l1 = 0.f;

    const __half2 sc = __float2half2_rn(0.125f * 1.4426950408889634f);
    const int wrow = warp * 16;
    const int grow = q0 + wrow;

    for (int kt = 0; kt < nkt; kt++) {
        if (kt + 1 < nkt) cp_wait<1>(); else cp_wait<0>();
        __syncthreads();
        const int cur = kt & 1;
        const int k0 = kt * 64;
        const uint32_t kBase = sK + (uint32_t)(cur * 64 * AST) * 4u + lmOff;
        const uint32_t vBase = sV + (uint32_t)(cur * 64 * AST) * 4u + lmOff;

        if (kt == 0) {
            const uint32_t* qp = Qs + (wrow + r4) * AST;
            #pragma unroll
            for (int p = 0; p < 4; p++) {
                qf[p][0] = h2scale(qp[p * 8 + c4], sc);
                qf[p][1] = h2scale(qp[8 * AST + p * 8 + c4], sc);
                qf[p][2] = h2scale(qp[p * 8 + c4 + 4], sc);
                qf[p][3] = h2scale(qp[8 * AST + p * 8 + c4 + 4], sc);
            }
        }

        if (k0 <= grow + 15) {
            // ---- S = Q K^T (log2 domain), K via ldmatrix ----
            float sacc[8][4];
            #pragma unroll
            for (int nt = 0; nt < 8; nt++)
                #pragma unroll
                for (int r = 0; r < 4; r++) sacc[nt][r] = 0.f;

            #pragma unroll
            for (int nt = 0; nt < 8; nt++) {
                uint32_t k01[4], k23[4];
                const uint32_t a = kBase + (uint32_t)(nt * 8 * AST) * 4u;
                ldsm4(k01, a);          // words 0..15  -> p0 b0,b1, p1 b0,b1
                ldsm4(k23, a + 64u);    // words 16..31 -> p2, p3
                mma_f16(sacc[nt], qf[0], &k01[0]);
                mma_f16(sacc[nt], qf[1], &k01[2]);
                mma_f16(sacc[nt], qf[2], &k23[0]);
                mma_f16(sacc[nt], qf[3], &k23[2]);
            }

            // causal mask (global frame)
            if (k0 + 63 > grow) {
                const int row0 = grow + r4;
                #pragma unroll
                for (int nt = 0; nt < 8; nt++) {
                    const int cb = k0 + nt * 8 + 2 * c4;
                    if (cb + 0 > row0)     sacc[nt][0] = -1e30f;
                    if (cb + 1 > row0)     sacc[nt][1] = -1e30f;
                    if (cb + 0 > row0 + 8) sacc[nt][2] = -1e30f;
                    if (cb + 1 > row0 + 8) sacc[nt][3] = -1e30f;
                }
            }

            // ---- online softmax (exp2), P packed to registers ----
            float rm0 = -1e30f, rm1 = -1e30f;
            #pragma unroll
            for (int nt = 0; nt < 8; nt++) {
                rm0 = fmaxf(rm0, fmaxf(sacc[nt][0], sacc[nt][1]));
                rm1 = fmaxf(rm1, fmaxf(sacc[nt][2], sacc[nt][3]));
            }
            rm0 = fmaxf(rm0, __shfl_xor_sync(~0u, rm0, 1));
            rm0 = fmaxf(rm0, __shfl_xor_sync(~0u, rm0, 2));
            rm1 = fmaxf(rm1, __shfl_xor_sync(~0u, rm1, 1));
            rm1 = fmaxf(rm1, __shfl_xor_sync(~0u, rm1, 2));

            const float mn0 = fmaxf(m0, rm0), mn1 = fmaxf(m1, rm1);
            const float f0 = exp2f(m0 - mn0), f1 = exp2f(m1 - mn1);
            m0 = mn0; m1 = mn1;

            float rs0 = 0.f, rs1 = 0.f;
            uint32_t ph[8][2];
            #pragma unroll
            for (int nt = 0; nt < 8; nt++) {
                float p0 = exp2f(sacc[nt][0] - mn0);
                float p1 = exp2f(sacc[nt][1] - mn0);
                float p2 = exp2f(sacc[nt][2] - mn1);
                float p3 = exp2f(sacc[nt][3] - mn1);
                rs0 += p0 + p1; rs1 += p2 + p3;
                __half2 w0 = __floats2half2_rn(p0, p1);
                __half2 w1 = __floats2half2_rn(p2, p3);
                ph[nt][0] = *(uint32_t*)&w0;    // rows r4
                ph[nt][1] = *(uint32_t*)&w1;    // rows r4+8
            }
            rs0 += __shfl_xor_sync(~0u, rs0, 1);
            rs0 += __shfl_xor_sync(~0u, rs0, 2);
            rs1 += __shfl_xor_sync(~0u, rs1, 1);
            rs1 += __shfl_xor_sync(~0u, rs1, 2);
            l0 = l0 * f0 + rs0;
            l1 = l1 * f1 + rs1;

            #pragma unroll
            for (int nt = 0; nt < 8; nt++) {
                oacc[nt][0] *= f0; oacc[nt][1] *= f0;
                oacc[nt][2] *= f1; oacc[nt][3] *= f1;
            }

            // ---- O += P V, P from registers, V via ldmatrix ----
            // A-fragment for key-chunk p: {ph[2p][0], ph[2p][1], ph[2p+1][0], ph[2p+1][1]}
            uint32_t af[4][4];
            #pragma unroll
            for (int p = 0; p < 4; p++) {
                af[p][0] = ph[2*p][0];
                af[p][1] = ph[2*p][1];
                af[p][2] = ph[2*p+1][0];
                af[p][3] = ph[2*p+1][1];
            }
            #pragma unroll
            for (int nt = 0; nt < 8; nt++) {
                uint32_t v01[4], v23[4];
                const uint32_t a = vBase + (uint32_t)(nt * 8 * AST) * 4u;
                ldsm4(v01, a);
                ldsm4(v23, a + 64u);
                mma_f16(oacc[nt], af[0], &v01[0]);
                mma_f16(oacc[nt], af[1], &v01[2]);
                mma_f16(oacc[nt], af[2], &v23[0]);
                mma_f16(oacc[nt], af[3], &v23[2]);
            }
        }

        __syncthreads();
        if (kt + 2 < nkt) { issue_kv(cur, (kt + 2) * 64); cp_commit(); }
    }

    // epilogue
    const float inv0 = 1.f / l0, inv1 = 1.f / l1;
    const int row0 = grow + r4;
    #pragma unroll
    for (int nt = 0; nt < 8; nt++) {
        const int col = h * HD + nt * 8 + 2 * c4;
        *(__half2*)(O + (size_t)(b * TD + row0) * CD + col) =
            __floats2half2_rn(oacc[nt][0] * inv0, oacc[nt][1] * inv0);
        *(__half2*)(O + (size_t)(b * TD + row0 + 8) * CD + col) =
            __floats2half2_rn(oacc[nt][2] * inv1, oacc[nt][3] * inv1);
    }
}

// ---------------------------------------------------------------------------
// Launch
// ---------------------------------------------------------------------------
extern "C" void kernel_launch(void* const* d_in, const int* in_sizes, int n_in,
                              void* d_out, int out_size)
{
    const float* x      = (const float*)d_in[0];
    const float* ln_a_g = (const float*)d_in[1];
    const float* ln_a_b = (const float*)d_in[2];
    const float* ln_b_g = (const float*)d_in[3];
    const float* ln_b_b = (const float*)d_in[4];
    const float* ln_c_g = (const float*)d_in[5];
    const float* ln_c_b = (const float*)d_in[6];
    const float* Wq = (const float*)d_in[7];  const float* bq = (const float*)d_in[8];
    const float* Wk = (const float*)d_in[9];  const float* bk = (const float*)d_in[10];
    const float* Wv = (const float*)d_in[11]; const float* bv = (const float*)d_in[12];
    const float* Wo = (const float*)d_in[13]; const float* bo = (const float*)d_in[14];
    const float* We = (const float*)d_in[15]; const float* be = (const float*)d_in[16];
    const float* Wd = (const float*)d_in[17]; const float* bd = (const float*)d_in[18];
    float* out = (float*)d_out;

    float *x2;
    __half *th, *t2h, *qh, *kh, *vt, *ctxh, *hh;
    __half2 *wqp, *wkp, *wvp, *wop, *wep, *wdp;
    cudaGetSymbolAddress((void**)&x2,   g_x2);
    cudaGetSymbolAddress((void**)&th,   g_th);
    cudaGetSymbolAddress((void**)&t2h,  g_t2h);
    cudaGetSymbolAddress((void**)&qh,   g_qh);
    cudaGetSymbolAddress((void**)&kh,   g_kh);
    cudaGetSymbolAddress((void**)&vt,   g_vt);
    cudaGetSymbolAddress((void**)&ctxh, g_ctxh);
    cudaGetSymbolAddress((void**)&hh,   g_hh);
    cudaGetSymbolAddress((void**)&wqp,  g_wqp);
    cudaGetSymbolAddress((void**)&wkp,  g_wkp);
    cudaGetSymbolAddress((void**)&wvp,  g_wvp);
    cudaGetSymbolAddress((void**)&wop,  g_wop);
    cudaGetSymbolAddress((void**)&wep,  g_wep);
    cudaGetSymbolAddress((void**)&wdp,  g_wdp);

    cudaFuncSetAttribute(attn_h, cudaFuncAttributeMaxDynamicSharedMemorySize,
                         ATTN_SMEM);
    cudaFuncSetAttribute(attn_h, cudaFuncAttributePreferredSharedMemoryCarveout,
                         100);

    // 0. fused weight conversion
    {
        const int total = 3 * (1 << 21);
        wconv_all<<<total / 256, 256>>>(Wq, Wk, Wv, Wo, We, Wd,
                                        wqp, wkp, wvp, wop, wep, wdp);
    }

    // 1. th = fp16(LN_b(LN_a(x)))
    ln2_kernel<<<NT, 256>>>(x, ln_a_g, ln_a_b, ln_b_g, ln_b_b, th);

    // 2. QKV (fused): q,k fp16 row-major; v fp16 transposed
    {
        dim3 grid(CD / 128, NT / 128, 3);
        gemm_h<<<grid, 256>>>(th, wqp, wkp, wvp, bq, bk, bv, nullptr,
                              nullptr, nullptr, nullptr,
                              qh, kh, vt, 1, NT, CD, CD, 0);
    }

    // 3. causal attention -> ctxh
    {
        dim3 grid(TD / 128, BD * HN);
        attn_h<<<grid, 256, ATTN_SMEM>>>(qh, kh, vt, ctxh);
    }

    // 4. x2 = x + ctx @ Wo + bo
    {
        dim3 grid(CD / 128, NT / 128, 1);
        gemm_h<<<grid, 256>>>(ctxh, wop, wop, wop, bo, bo, bo, x,
                              x2, x2, x2, nullptr, nullptr, nullptr,
                              0, NT, CD, CD, 0);
    }

    // 5. t2h = fp16(LN_c(x2))
    ln1_kernel<<<NT, 256>>>(x2, ln_c_g, ln_c_b, t2h);

    // 6. hh = fp16(silu(t2 @ We + be))
    {
        dim3 grid(DFFD / 128, NT / 128, 1);
        gemm_h<<<grid, 256>>>(t2h, wep, wep, wep, be, be, be, nullptr,
                              nullptr, nullptr, nullptr, hh, hh, hh,
                              0, NT, DFFD, CD, 1);
    }

    // 7. out = x2 + h @ Wd + bd
    {
        dim3 grid(CD / 128, NT / 128, 1);
        gemm_h<<<grid, 256>>>(hh, wdp, wdp, wdp, bd, bd, bd, x2,
                              out, out, out, nullptr, nullptr, nullptr,
                              0, NT, CD, DFFD, 0);
    }
}

// round 15
// speedup vs baseline: 1.0985x; 1.0779x over previous
#include <cuda_runtime.h>
#include <cuda_fp16.h>
#include <math.h>
#include <stdint.h>

// Problem dims
#define BD   2
#define TD   2048
#define CD   1024
#define HN   16
#define HD   64
#define DFFD 4096
#define NT   (BD * TD)   // 4096 tokens

// ---------------------------------------------------------------------------
// Scratch (device globals)
// ---------------------------------------------------------------------------
__device__ float  g_x2 [(size_t)NT * CD];
__device__ __half g_th  [(size_t)NT * CD];
__device__ __half g_t2h [(size_t)NT * CD];
__device__ __half g_qh  [(size_t)NT * CD];
__device__ __half g_kh  [(size_t)NT * CD];
__device__ __half g_vh  [(size_t)NT * CD];    // V row-major [token][C] fp16
__device__ __half g_ctxh[(size_t)NT * CD];
__device__ __half g_hh  [(size_t)NT * DFFD];
// k-pair-packed fp16 weights
__device__ __half2 g_wqp[(CD/2) * CD];
__device__ __half2 g_wkp[(CD/2) * CD];
__device__ __half2 g_wvp[(CD/2) * CD];
__device__ __half2 g_wop[(CD/2) * CD];
__device__ __half2 g_wep[(CD/2) * DFFD];
__device__ __half2 g_wdp[(DFFD/2) * CD];

// ---------------------------------------------------------------------------
// Helpers
// ---------------------------------------------------------------------------
__device__ __forceinline__ void cp16(uint32_t smem_dst, const void* gptr) {
    asm volatile("cp.async.cg.shared.global [%0], [%1], 16;\n"
                 :: "r"(smem_dst), "l"(gptr));
}
__device__ __forceinline__ void cp_commit() {
    asm volatile("cp.async.commit_group;\n" ::: "memory");
}
template <int N>
__device__ __forceinline__ void cp_wait() {
    asm volatile("cp.async.wait_group %0;\n" :: "n"(N) : "memory");
}
__device__ __forceinline__ void mma_f16(float* c, const uint32_t* a, const uint32_t* b) {
    asm volatile(
        "mma.sync.aligned.m16n8k16.row.col.f32.f16.f16.f32 "
        "{%0,%1,%2,%3},{%4,%5,%6,%7},{%8,%9},{%0,%1,%2,%3};"
        : "+f"(c[0]), "+f"(c[1]), "+f"(c[2]), "+f"(c[3])
        : "r"(a[0]), "r"(a[1]), "r"(a[2]), "r"(a[3]), "r"(b[0]), "r"(b[1]));
}
__device__ __forceinline__ void ldsm4(uint32_t* r, uint32_t addr) {
    asm volatile(
        "ldmatrix.sync.aligned.m8n8.x4.shared.b16 {%0,%1,%2,%3}, [%4];"
        : "=r"(r[0]), "=r"(r[1]), "=r"(r[2]), "=r"(r[3]) : "r"(addr));
}
__device__ __forceinline__ void ldsm4t(uint32_t* r, uint32_t addr) {
    asm volatile(
        "ldmatrix.sync.aligned.m8n8.x4.trans.shared.b16 {%0,%1,%2,%3}, [%4];"
        : "=r"(r[0]), "=r"(r[1]), "=r"(r[2]), "=r"(r[3]) : "r"(addr));
}
__device__ __forceinline__ uint32_t h2scale(uint32_t w, __half2 s) {
    __half2 a = *(__half2*)&w;
    a = __hmul2(a, s);
    return *(uint32_t*)&a;
}

// ---------------------------------------------------------------------------
// Fused weight conversion (one launch)
// ---------------------------------------------------------------------------
__global__ __launch_bounds__(256) void wconv_all(
    const float* __restrict__ Wq, const float* __restrict__ Wk,
    const float* __restrict__ Wv, const float* __restrict__ Wo,
    const float* __restrict__ We, const float* __restrict__ Wd,
    __half2* __restrict__ oq, __half2* __restrict__ ok,
    __half2* __restrict__ ov, __half2* __restrict__ oo,
    __half2* __restrict__ oe, __half2* __restrict__ od)
{
    int idx = blockIdx.x * 256 + threadIdx.x;
    const float* W;
    __half2* out;
    int nshift, i;
    if (idx < (1 << 21)) {
        const int m = idx >> 19;
        i = idx & ((1 << 19) - 1);
        W   = (m == 0) ? Wq : (m == 1) ? Wk : (m == 2) ? Wv : Wo;
        out = (m == 0) ? oq : (m == 1) ? ok : (m == 2) ? ov : oo;
        nshift = 10;
    } else if (idx < (2 << 21)) {
        i = idx - (1 << 21);
        W = We; out = oe; nshift = 12;
    } else {
        i = idx - (2 << 21);
        W = Wd; out = od; nshift = 10;
    }
    const int kk = i >> nshift;
    const int n  = i & ((1 << nshift) - 1);
    const size_t base = ((size_t)(2 * kk) << nshift) + n;
    out[i] = __floats2half2_rn(W[base], W[base + ((size_t)1 << nshift)]);
}

// ---------------------------------------------------------------------------
// Fused double LayerNorm -> fp16 out
// ---------------------------------------------------------------------------
__global__ __launch_bounds__(256) void ln2_kernel(
    const float* __restrict__ x,
    const float* __restrict__ ga, const float* __restrict__ ba,
    const float* __restrict__ gb, const float* __restrict__ bb,
    __half* __restrict__ out)
{
    __shared__ float red[16];
    __shared__ float bc[2];
    const int row = blockIdx.x, tid = threadIdx.x;
    const float4 v = *(const float4*)(x + (size_t)row * CD + tid * 4);

    float s  = v.x + v.y + v.z + v.w;
    float s2 = v.x*v.x + v.y*v.y + v.z*v.z + v.w*v.w;
    #pragma unroll
    for (int o = 16; o; o >>= 1) {
        s  += __shfl_xor_sync(~0u, s,  o);
        s2 += __shfl_xor_sync(~0u, s2, o);
    }
    if ((tid & 31) == 0) { red[(tid >> 5)*2] = s; red[(tid >> 5)*2 + 1] = s2; }
    __syncthreads();
    if (tid == 0) {
        float a = 0.f, b2 = 0.f;
        #pragma unroll
        for (int w = 0; w < 8; w++) { a += red[w*2]; b2 += red[w*2 + 1]; }
        float mu  = a * (1.f / CD);
        float var = b2 * (1.f / CD) - mu * mu;
        bc[0] = mu; bc[1] = rsqrtf(var + 1e-5f);
    }
    __syncthreads();
    float mu = bc[0], rstd = bc[1];
    __syncthreads();

    const float4 g4 = *(const float4*)(ga + tid * 4);
    const float4 b4 = *(const float4*)(ba + tid * 4);
    float y[4];
    y[0] = (v.x - mu) * rstd * g4.x + b4.x;
    y[1] = (v.y - mu) * rstd * g4.y + b4.y;
    y[2] = (v.z - mu) * rstd * g4.z + b4.z;
    y[3] = (v.w - mu) * rstd * g4.w + b4.w;

    s  = y[0] + y[1] + y[2] + y[3];
    s2 = y[0]*y[0] + y[1]*y[1] + y[2]*y[2] + y[3]*y[3];
    #pragma unroll
    for (int o = 16; o; o >>= 1) {
        s  += __shfl_xor_sync(~0u, s,  o);
        s2 += __shfl_xor_sync(~0u, s2, o);
    }
    if ((tid & 31) == 0) { red[(tid >> 5)*2] = s; red[(tid >> 5)*2 + 1] = s2; }
    __syncthreads();
    if (tid == 0) {
        float a = 0.f, b2 = 0.f;
        #pragma unroll
        for (int w = 0; w < 8; w++) { a += red[w*2]; b2 += red[w*2 + 1]; }
        float mu2  = a * (1.f / CD);
        float var2 = b2 * (1.f / CD) - mu2 * mu2;
        bc[0] = mu2; bc[1] = rsqrtf(var2 + 1e-5f);
    }
    __syncthreads();
    mu = bc[0]; rstd = bc[1];

    const float4 g24 = *(const float4*)(gb + tid * 4);
    const float4 b24 = *(const float4*)(bb + tid * 4);
    float o0 = (y[0] - mu) * rstd * g24.x + b24.x;
    float o1 = (y[1] - mu) * rstd * g24.y + b24.y;
    float o2 = (y[2] - mu) * rstd * g24.z + b24.z;
    float o3 = (y[3] - mu) * rstd * g24.w + b24.w;
    __half* op = out + (size_t)row * CD + tid * 4;
    *(__half2*)(op)     = __floats2half2_rn(o0, o1);
    *(__half2*)(op + 2) = __floats2half2_rn(o2, o3);
}

__global__ __launch_bounds__(256) void ln1_kernel(
    const float* __restrict__ x,
    const float* __restrict__ g, const float* __restrict__ b,
    __half* __restrict__ out)
{
    __shared__ float red[16];
    __shared__ float bc[2];
    const int row = blockIdx.x, tid = threadIdx.x;
    const float4 v = *(const float4*)(x + (size_t)row * CD + tid * 4);

    float s  = v.x + v.y + v.z + v.w;
    float s2 = v.x*v.x + v.y*v.y + v.z*v.z + v.w*v.w;
    #pragma unroll
    for (int o = 16; o; o >>= 1) {
        s  += __shfl_xor_sync(~0u, s,  o);
        s2 += __shfl_xor_sync(~0u, s2, o);
    }
    if ((tid & 31) == 0) { red[(tid >> 5)*2] = s; red[(tid >> 5)*2 + 1] = s2; }
    __syncthreads();
    if (tid == 0) {
        float a = 0.f, b2 = 0.f;
        #pragma unroll
        for (int w = 0; w < 8; w++) { a += red[w*2]; b2 += red[w*2 + 1]; }
        float mu  = a * (1.f / CD);
        float var = b2 * (1.f / CD) - mu * mu;
        bc[0] = mu; bc[1] = rsqrtf(var + 1e-5f);
    }
    __syncthreads();
    const float mu = bc[0], rstd = bc[1];
    const float4 g4 = *(const float4*)(g + tid * 4);
    const float4 b4 = *(const float4*)(b + tid * 4);
    float o0 = (v.x - mu) * rstd * g4.x + b4.x;
    float o1 = (v.y - mu) * rstd * g4.y + b4.y;
    float o2 = (v.z - mu) * rstd * g4.z + b4.z;
    float o3 = (v.w - mu) * rstd * g4.w + b4.w;
    __half* op = out + (size_t)row * CD + tid * 4;
    *(__half2*)(op)     = __floats2half2_rn(o0, o1);
    *(__half2*)(op + 2) = __floats2half2_rn(o2, o3);
}

// ---------------------------------------------------------------------------
// FP16 tensor-core GEMM, 4-stage cp.async ring (dynamic smem, immediate slots)
// 128x128 tile, BK=32, 8 warps (2x4), warp 64x32, ldmatrix A-fragments.
//   A stage: 128 rows x 20 words (10240 B); B stage: 16 x 128 words (8192 B).
// ---------------------------------------------------------------------------
#define GH_ASTG 10240u
#define GH_BSTG 8192u
#define GH_SMEM (4 * (GH_ASTG + GH_BSTG))   // 73728

__global__ __launch_bounds__(256, 2) void gemm_h(
    const __half* __restrict__ A,
    const __half2* __restrict__ Wp0, const __half2* __restrict__ Wp1,
    const __half2* __restrict__ Wp2,
    const float* __restrict__ b0, const float* __restrict__ b1,
    const float* __restrict__ b2,
    const float* __restrict__ res,
    float* __restrict__ C0, float* __restrict__ C1, float* __restrict__ C2,
    __half* __restrict__ H0, __half* __restrict__ H1, __half* __restrict__ H2,
    int M, int N, int K, int act)
{
    extern __shared__ uint32_t gsm[];
    uint32_t* Bsm = gsm + 4 * 2560;          // after 4 A stages (words)

    const int z = blockIdx.z;
    const __half2* Wp  = (z == 0) ? Wp0 : (z == 1) ? Wp1 : Wp2;
    const float*  bias = (z == 0) ? b0  : (z == 1) ? b1  : b2;
    float*        Cc   = (z == 0) ? C0  : (z == 1) ? C1  : C2;
    __half*       Hh   = (z == 0) ? H0  : (z == 1) ? H1  : H2;

    const int tid  = threadIdx.x;
    const int lane = tid & 31;
    const int warp = tid >> 5;
    const int wm = warp & 1;
    const int wn = warp >> 1;
    const int bm = blockIdx.y * 128;
    const int bn = blockIdx.x * 128;

    const int ar1 = tid >> 2,          aq1 = tid & 3;
    const int ar2 = (tid + 256) >> 2,  aq2 = (tid + 256) & 3;
    const int bk1 = tid >> 5,          bn1 = tid & 31;
    const int bk2 = (tid + 256) >> 5,  bn2 = (tid + 256) & 31;

    const uint32_t sA = (uint32_t)__cvta_generic_to_shared(gsm);
    const uint32_t sB = sA + 4u * GH_ASTG;
    const uint32_t aD1 = sA + (uint32_t)(ar1 * 20 + aq1 * 4) * 4u;
    const uint32_t aD2 = sA + (uint32_t)(ar2 * 20 + aq2 * 4) * 4u;
    const uint32_t bD1 = sB + (uint32_t)(bk1 * 128 + ((bn1 * 4) ^ (8 * bk1))) * 4u;
    const uint32_t bD2 = sB + (uint32_t)(bk2 * 128 + ((bn2 * 4) ^ (8 * bk2))) * 4u;

    const __half*  gA1 = A + (size_t)(bm + ar1) * K + aq1 * 8;
    const __half*  gA2 = A + (size_t)(bm + ar2) * K + aq2 * 8;
    const __half2* gB1 = Wp + (size_t)bk1 * N + bn + bn1 * 4;
    const __half2* gB2 = Wp + (size_t)bk2 * N + bn + bn2 * 4;
    const size_t bStep = (size_t)16 * N;

    const int mi = lane >> 3;
    const int rr = lane & 7;
    uint32_t aL[4];
    #pragma unroll
    for (int mf = 0; mf < 4; mf++) {
        const int m = wm * 64 + mf * 16 + (mi & 1) * 8 + rr;
        aL[mf] = sA + (uint32_t)(m * 20 + (mi >> 1) * 4) * 4u;
    }

    float acc[4][4][4];
    #pragma unroll
    for (int i = 0; i < 4; i++)
        #pragma unroll
        for (int j = 0; j < 4; j++)
            #pragma unroll
            for (int r = 0; r < 4; r++) acc[i][j][r] = 0.f;

    auto issue = [&](uint32_t slot) {
        cp16(aD1 + slot * GH_ASTG, gA1);
        cp16(aD2 + slot * GH_ASTG, gA2);
        cp16(bD1 + slot * GH_BSTG, gB1);
        cp16(bD2 + slot * GH_BSTG, gB2);
        gA1 += 32; gA2 += 32; gB1 += bStep; gB2 += bStep;
    };

    issue(0); cp_commit();
    issue(1); cp_commit();
    issue(2); cp_commit();
    issue(3); cp_commit();

    const int nK = K >> 5;          // 32 or 128: divisible by 4
    const int r4 = lane >> 2;
    const int c4 = lane & 3;
    const int nb0 = wn * 32 + r4;

    for (int kt = 0; kt < nK; kt += 4) {
        #pragma unroll
        for (int s = 0; s < 4; s++) {
            cp_wait<3>();
            __syncthreads();
            const uint32_t curA = (uint32_t)s * GH_ASTG;
            const uint32_t* Bp = Bsm + s * 2048;

            #pragma unroll
            for (int p = 0; p < 2; p++) {
                uint32_t af[4][4], bf[4][2];
                #pragma unroll
                for (int mf = 0; mf < 4; mf++)
                    ldsm4(af[mf], aL[mf] + curA + (uint32_t)(p * 32));
                #pragma unroll
                for (int nf = 0; nf < 4; nf++) {
                    const int n = nb0 + nf * 8;
                    bf[nf][0] = Bp[(p * 8 + c4) * 128     + (n ^ (64 * p + 8 * c4))];
                    bf[nf][1] = Bp[(p * 8 + c4 + 4) * 128 + (n ^ (64 * p + 8 * c4 + 32))];
                }
                #pragma unroll
                for (int mf = 0; mf < 4; mf++)
                    #pragma unroll
                    for (int nf = 0; nf < 4; nf++)
                        mma_f16(acc[mf][nf], af[mf], bf[nf]);
            }
            __syncthreads();
            if (kt + s + 4 < nK) issue((uint32_t)s);
            cp_commit();
        }
    }

    // epilogue
    #pragma unroll
    for (int mf = 0; mf < 4; mf++) {
        #pragma unroll
        for (int nf = 0; nf < 4; nf++) {
            const int col = bn + wn * 32 + nf * 8 + c4 * 2;
            const float bx = bias[col], by = bias[col + 1];
            #pragma unroll
            for (int h = 0; h < 2; h++) {
                const int row = bm + wm * 64 + mf * 16 + r4 + h * 8;
                float ox = acc[mf][nf][h * 2 + 0] + bx;
                float oy = acc[mf][nf][h * 2 + 1] + by;
                if (act) {
                    ox *= 1.f / (1.f + __expf(-ox));
                    oy *= 1.f / (1.f + __expf(-oy));
                }
                const size_t off = (size_t)row * N + col;
                if (res) {
                    const float2 rr2 = *(const float2*)(res + off);
                    ox += rr2.x; oy += rr2.y;
                }
                if (Cc) {
                    float2 o; o.x = ox; o.y = oy;
                    *(float2*)(Cc + off) = o;
                }
                if (Hh) *(__half2*)(Hh + off) = __floats2half2_rn(ox, oy);
            }
        }
    }
}

// ---------------------------------------------------------------------------
// FP16 flash attention v4: 128-row Q tile, 256 threads, register-resident P,
// ldmatrix K fragments, ldmatrix.trans V fragments (V row-major [key][dim]),
// exp2 softmax, global-frame causal.
// ---------------------------------------------------------------------------
#define AST 36
#define ATTN_SMEM ((128*AST + 2*64*AST + 2*64*AST) * 4)

__global__ __launch_bounds__(256, 2) void attn_h(
    const __half* __restrict__ Qh, const __half* __restrict__ Kh,
    const __half* __restrict__ Vh, __half* __restrict__ O)
{
    extern __shared__ uint32_t smA[];
    uint32_t* Qs = smA;
    uint32_t* Ks = Qs + 128 * AST;
    uint32_t* Vs = Ks + 2 * 64 * AST;     // [2][64 keys][36] row-major [k][n]

    const int bh = blockIdx.y;
    const int b = bh >> 4, h = bh & 15;
    const int qt = blockIdx.x;
    const int q0 = qt * 128;
    const int tid = threadIdx.x;
    const int lane = tid & 31;
    const int warp = tid >> 5;
    const int r4 = lane >> 2;
    const int c4 = lane & 3;

    const __half* qg = Qh + (size_t)(b * TD + q0) * CD + h * HD;
    const __half* kg = Kh + (size_t)b * TD * CD + h * HD;
    const __half* vg = Vh + (size_t)b * TD * CD + h * HD;

    const uint32_t sQ = (uint32_t)__cvta_generic_to_shared(Qs);
    const uint32_t sK = (uint32_t)__cvta_generic_to_shared(Ks);
    const uint32_t sV = (uint32_t)__cvta_generic_to_shared(Vs);

    #pragma unroll
    for (int i = 0; i < 4; i++) {
        const int idx = tid + i * 256;
        const int row = idx >> 3, cc = idx & 7;
        cp16(sQ + (uint32_t)(row * AST + cc * 4) * 4u, qg + row * CD + cc * 8);
    }
    auto issue_kv = [&](int buf, int k0) {
        #pragma unroll
        for (int i = 0; i < 2; i++) {
            const int idx = tid + i * 256;
            const int row = idx >> 3, cc = idx & 7;
            const size_t g = (size_t)(k0 + row) * CD + cc * 8;
            cp16(sK + (uint32_t)(buf * 64 * AST + row * AST + cc * 4) * 4u, kg + g);
            cp16(sV + (uint32_t)(buf * 64 * AST + row * AST + cc * 4) * 4u, vg + g);
        }
    };
    const int nkt = 2 * qt + 2;
    issue_kv(0, 0);
    cp_commit();
    if (nkt > 1) { issue_kv(1, 64); cp_commit(); }

    // K ldmatrix: row (lane&7), word group (lane>>3)
    const uint32_t lmOff = (uint32_t)((lane & 7) * AST + (lane >> 3) * 4) * 4u;
    // V trans ldmatrix: row = lane (32 consecutive key rows)
    const uint32_t lmTOff = (uint32_t)(lane * AST) * 4u;

    uint32_t qf[4][4];
    float oacc[8][4];
    #pragma unroll
    for (int nt = 0; nt < 8; nt++)
        #pragma unroll
        for (int r = 0; r < 4; r++) oacc[nt][r] = 0.f;
    float m0 = -1e30f, m1 = -1e30f, l0 = 0.f, l1 = 0.f;

    const __half2 sc = __float2half2_rn(0.125f * 1.4426950408889634f);
    const int wrow = warp * 16;
    const int grow = q0 + wrow;

    for (int kt = 0; kt < nkt; kt++) {
        if (kt + 1 < nkt) cp_wait<1>(); else cp_wait<0>();
        __syncthreads();
        const int cur = kt & 1;
        const int k0 = kt * 64;
        const uint32_t kBase = sK + (uint32_t)(cur * 64 * AST) * 4u + lmOff;
        const uint32_t vBase = sV + (uint32_t)(cur * 64 * AST) * 4u + lmTOff;

        if (kt == 0) {
            const uint32_t* qp = Qs + (wrow + r4) * AST;
            #pragma unroll
            for (int p = 0; p < 4; p++) {
                qf[p][0] = h2scale(qp[p * 8 + c4], sc);
                qf[p][1] = h2scale(qp[8 * AST + p * 8 + c4], sc);
                qf[p][2] = h2scale(qp[p * 8 + c4 + 4], sc);
                qf[p][3] = h2scale(qp[8 * AST + p * 8 + c4 + 4], sc);
            }
        }

        if (k0 <= grow + 15) {
            // ---- S = Q K^T (log2 domain) ----
            float sacc[8][4];
            #pragma unroll
            for (int nt = 0; nt < 8; nt++)
                #pragma unroll
                for (int r = 0; r < 4; r++) sacc[nt][r] = 0.f;

            #pragma unroll
            for (int nt = 0; nt < 8; nt++) {
                uint32_t k01[4], k23[4];
                const uint32_t a = kBase + (uint32_t)(nt * 8 * AST) * 4u;
                ldsm4(k01, a);
                ldsm4(k23, a + 64u);
                mma_f16(sacc[nt], qf[0], &k01[0]);
                mma_f16(sacc[nt], qf[1], &k01[2]);
                mma_f16(sacc[nt], qf[2], &k23[0]);
                mma_f16(sacc[nt], qf[3], &k23[2]);
            }

            if (k0 + 63 > grow) {
                const int row0 = grow + r4;
                #pragma unroll
                for (int nt = 0; nt < 8; nt++) {
                    const int cb = k0 + nt * 8 + 2 * c4;
                    if (cb + 0 > row0)     sacc[nt][0] = -1e30f;
                    if (cb + 1 > row0)     sacc[nt][1] = -1e30f;
                    if (cb + 0 > row0 + 8) sacc[nt][2] = -1e30f;
                    if (cb + 1 > row0 + 8) sacc[nt][3] = -1e30f;
                }
            }

            float rm0 = -1e30f, rm1 = -1e30f;
            #pragma unroll
            for (int nt = 0; nt < 8; nt++) {
                rm0 = fmaxf(rm0, fmaxf(sacc[nt][0], sacc[nt][1]));
                rm1 = fmaxf(rm1, fmaxf(sacc[nt][2], sacc[nt][3]));
            }
            rm0 = fmaxf(rm0, __shfl_xor_sync(~0u, rm0, 1));
            rm0 = fmaxf(rm0, __shfl_xor_sync(~0u, rm0, 2));
            rm1 = fmaxf(rm1, __shfl_xor_sync(~0u, rm1, 1));
            rm1 = fmaxf(rm1, __shfl_xor_sync(~0u, rm1, 2));

            const float mn0 = fmaxf(m0, rm0), mn1 = fmaxf(m1, rm1);
            const float f0 = exp2f(m0 - mn0), f1 = exp2f(m1 - mn1);
            m0 = mn0; m1 = mn1;

            float rs0 = 0.f, rs1 = 0.f;
            uint32_t ph[8][2];
            #pragma unroll
            for (int nt = 0; nt < 8; nt++) {
                float p0 = exp2f(sacc[nt][0] - mn0);
                float p1 = exp2f(sacc[nt][1] - mn0);
                float p2 = exp2f(sacc[nt][2] - mn1);
                float p3 = exp2f(sacc[nt][3] - mn1);
                rs0 += p0 + p1; rs1 += p2 + p3;
                __half2 w0 = __floats2half2_rn(p0, p1);
                __half2 w1 = __floats2half2_rn(p2, p3);
                ph[nt][0] = *(uint32_t*)&w0;
                ph[nt][1] = *(uint32_t*)&w1;
            }
            rs0 += __shfl_xor_sync(~0u, rs0, 1);
            rs0 += __shfl_xor_sync(~0u, rs0, 2);
            rs1 += __shfl_xor_sync(~0u, rs1, 1);
            rs1 += __shfl_xor_sync(~0u, rs1, 2);
            l0 = l0 * f0 + rs0;
            l1 = l1 * f1 + rs1;

            #pragma unroll
            for (int nt = 0; nt < 8; nt++) {
                oacc[nt][0] *= f0; oacc[nt][1] *= f0;
                oacc[nt][2] *= f1; oacc[nt][3] *= f1;
            }

            // ---- O += P V:  P in regs; V via ldmatrix.trans ----
            uint32_t af[4][4];
            #pragma unroll
            for (int p = 0; p < 4; p++) {
                af[p][0] = ph[2*p][0];
                af[p][1] = ph[2*p][1];
                af[p][2] = ph[2*p+1][0];
                af[p][3] = ph[2*p+1][1];
            }
            #pragma unroll
            for (int nt = 0; nt < 8; nt++) {
                uint32_t v0[4], v1[4];
                const uint32_t a = vBase + (uint32_t)(nt * 4) * 4u;
                ldsm4t(v0, a);                                    // keys 0..31
                ldsm4t(v1, a + (uint32_t)(32 * AST) * 4u);        // keys 32..63
                mma_f16(oacc[nt], af[0], &v0[0]);
                mma_f16(oacc[nt], af[1], &v0[2]);
                mma_f16(oacc[nt], af[2], &v1[0]);
                mma_f16(oacc[nt], af[3], &v1[2]);
            }
        }

        __syncthreads();
        if (kt + 2 < nkt) { issue_kv(cur, (kt + 2) * 64); cp_commit(); }
    }

    const float inv0 = 1.f / l0, inv1 = 1.f / l1;
    const int row0 = grow + r4;
    #pragma unroll
    for (int nt = 0; nt < 8; nt++) {
        const int col = h * HD + nt * 8 + 2 * c4;
        *(__half2*)(O + (size_t)(b * TD + row0) * CD + col) =
            __floats2half2_rn(oacc[nt][0] * inv0, oacc[nt][1] * inv0);
        *(__half2*)(O + (size_t)(b * TD + row0 + 8) * CD + col) =
            __floats2half2_rn(oacc[nt][2] * inv1, oacc[nt][3] * inv1);
    }
}

// ---------------------------------------------------------------------------
// Launch
// ---------------------------------------------------------------------------
extern "C" void kernel_launch(void* const* d_in, const int* in_sizes, int n_in,
                              void* d_out, int out_size)
{
    const float* x      = (const float*)d_in[0];
    const float* ln_a_g = (const float*)d_in[1];
    const float* ln_a_b = (const float*)d_in[2];
    const float* ln_b_g = (const float*)d_in[3];
    const float* ln_b_b = (const float*)d_in[4];
    const float* ln_c_g = (const float*)d_in[5];
    const float* ln_c_b = (const float*)d_in[6];
    const float* Wq = (const float*)d_in[7];  const float* bq = (const float*)d_in[8];
    const float* Wk = (const float*)d_in[9];  const float* bk = (const float*)d_in[10];
    const float* Wv = (const float*)d_in[11]; const float* bv = (const float*)d_in[12];
    const float* Wo = (const float*)d_in[13]; const float* bo = (const float*)d_in[14];
    const float* We = (const float*)d_in[15]; const float* be = (const float*)d_in[16];
    const float* Wd = (const float*)d_in[17]; const float* bd = (const float*)d_in[18];
    float* out = (float*)d_out;

    float *x2;
    __half *th, *t2h, *qh, *kh, *vh, *ctxh, *hh;
    __half2 *wqp, *wkp, *wvp, *wop, *wep, *wdp;
    cudaGetSymbolAddress((void**)&x2,   g_x2);
    cudaGetSymbolAddress((void**)&th,   g_th);
    cudaGetSymbolAddress((void**)&t2h,  g_t2h);
    cudaGetSymbolAddress((void**)&qh,   g_qh);
    cudaGetSymbolAddress((void**)&kh,   g_kh);
    cudaGetSymbolAddress((void**)&vh,   g_vh);
    cudaGetSymbolAddress((void**)&ctxh, g_ctxh);
    cudaGetSymbolAddress((void**)&hh,   g_hh);
    cudaGetSymbolAddress((void**)&wqp,  g_wqp);
    cudaGetSymbolAddress((void**)&wkp,  g_wkp);
    cudaGetSymbolAddress((void**)&wvp,  g_wvp);
    cudaGetSymbolAddress((void**)&wop,  g_wop);
    cudaGetSymbolAddress((void**)&wep,  g_wep);
    cudaGetSymbolAddress((void**)&wdp,  g_wdp);

    cudaFuncSetAttribute(attn_h, cudaFuncAttributeMaxDynamicSharedMemorySize,
                         ATTN_SMEM);
    cudaFuncSetAttribute(attn_h, cudaFuncAttributePreferredSharedMemoryCarveout,
                         100);
    cudaFuncSetAttribute(gemm_h, cudaFuncAttributeMaxDynamicSharedMemorySize,
                         GH_SMEM);
    cudaFuncSetAttribute(gemm_h, cudaFuncAttributePreferredSharedMemoryCarveout,
                         100);

    // 0. fused weight conversion
    {
        const int total = 3 * (1 << 21);
        wconv_all<<<total / 256, 256>>>(Wq, Wk, Wv, Wo, We, Wd,
                                        wqp, wkp, wvp, wop, wep, wdp);
    }

    // 1. th = fp16(LN_b(LN_a(x)))
    ln2_kernel<<<NT, 256>>>(x, ln_a_g, ln_a_b, ln_b_g, ln_b_b, th);

    // 2. QKV (fused): q,k,v all fp16 row-major
    {
        dim3 grid(CD / 128, NT / 128, 3);
        gemm_h<<<grid, 256, GH_SMEM>>>(th, wqp, wkp, wvp, bq, bk, bv, nullptr,
                                       nullptr, nullptr, nullptr,
                                       qh, kh, vh, NT, CD, CD, 0);
    }

    // 3. causal attention -> ctxh
    {
        dim3 grid(TD / 128, BD * HN);
        attn_h<<<grid, 256, ATTN_SMEM>>>(qh, kh, vh, ctxh);
    }

    // 4. x2 = x + ctx @ Wo + bo
    {
        dim3 grid(CD / 128, NT / 128, 1);
        gemm_h<<<grid, 256, GH_SMEM>>>(ctxh, wop, wop, wop, bo, bo, bo, x,
                                       x2, x2, x2, nullptr, nullptr, nullptr,
                                       NT, CD, CD, 0);
    }

    // 5. t2h = fp16(LN_c(x2))
    ln1_kernel<<<NT, 256>>>(x2, ln_c_g, ln_c_b, t2h);

    // 6. hh = fp16(silu(t2 @ We + be))
    {
        dim3 grid(DFFD / 128, NT / 128, 1);
        gemm_h<<<grid, 256, GH_SMEM>>>(t2h, wep, wep, wep, be, be, be, nullptr,
                                       nullptr, nullptr, nullptr, hh, hh, hh,
                                       NT, DFFD, CD, 1);
    }

    // 7. out = x2 + h @ Wd + bd
    {
        dim3 grid(CD / 128, NT / 128, 1);
        gemm_h<<<grid, 256, GH_SMEM>>>(hh, wdp, wdp, wdp, bd, bd, bd, x2,
                                       out, out, out, nullptr, nullptr, nullptr,
                                       NT, CD, DFFD, 0);
    }
}

// round 16
// speedup vs baseline: 1.1260x; 1.0250x over previous
#include <cuda_runtime.h>
#include <cuda_fp16.h>
#include <math.h>
#include <stdint.h>

// Problem dims
#define BD   2
#define TD   2048
#define CD   1024
#define HN   16
#define HD   64
#define DFFD 4096
#define NT   (BD * TD)   // 4096 tokens

// ---------------------------------------------------------------------------
// Scratch (device globals)
// ---------------------------------------------------------------------------
__device__ float  g_x2 [(size_t)NT * CD];
__device__ __half g_th  [(size_t)NT * CD];
__device__ __half g_t2h [(size_t)NT * CD];
__device__ __half g_qh  [(size_t)NT * CD];
__device__ __half g_kh  [(size_t)NT * CD];
__device__ __half g_vh  [(size_t)NT * CD];    // V row-major [token][C] fp16
__device__ __half g_ctxh[(size_t)NT * CD];
__device__ __half g_hh  [(size_t)NT * DFFD];
// k-pair-packed fp16 weights
__device__ __half2 g_wqp[(CD/2) * CD];
__device__ __half2 g_wkp[(CD/2) * CD];
__device__ __half2 g_wvp[(CD/2) * CD];
__device__ __half2 g_wop[(CD/2) * CD];
__device__ __half2 g_wep[(CD/2) * DFFD];
__device__ __half2 g_wdp[(DFFD/2) * CD];

// ---------------------------------------------------------------------------
// Helpers
// ---------------------------------------------------------------------------
__device__ __forceinline__ void cp16(uint32_t smem_dst, const void* gptr) {
    asm volatile("cp.async.cg.shared.global [%0], [%1], 16;\n"
                 :: "r"(smem_dst), "l"(gptr));
}
__device__ __forceinline__ void cp_commit() {
    asm volatile("cp.async.commit_group;\n" ::: "memory");
}
template <int N>
__device__ __forceinline__ void cp_wait() {
    asm volatile("cp.async.wait_group %0;\n" :: "n"(N) : "memory");
}
__device__ __forceinline__ void mma_f16(float* c, const uint32_t* a, const uint32_t* b) {
    asm volatile(
        "mma.sync.aligned.m16n8k16.row.col.f32.f16.f16.f32 "
        "{%0,%1,%2,%3},{%4,%5,%6,%7},{%8,%9},{%0,%1,%2,%3};"
        : "+f"(c[0]), "+f"(c[1]), "+f"(c[2]), "+f"(c[3])
        : "r"(a[0]), "r"(a[1]), "r"(a[2]), "r"(a[3]), "r"(b[0]), "r"(b[1]));
}
__device__ __forceinline__ void ldsm4(uint32_t* r, uint32_t addr) {
    asm volatile(
        "ldmatrix.sync.aligned.m8n8.x4.shared.b16 {%0,%1,%2,%3}, [%4];"
        : "=r"(r[0]), "=r"(r[1]), "=r"(r[2]), "=r"(r[3]) : "r"(addr));
}
__device__ __forceinline__ void ldsm4t(uint32_t* r, uint32_t addr) {
    asm volatile(
        "ldmatrix.sync.aligned.m8n8.x4.trans.shared.b16 {%0,%1,%2,%3}, [%4];"
        : "=r"(r[0]), "=r"(r[1]), "=r"(r[2]), "=r"(r[3]) : "r"(addr));
}
__device__ __forceinline__ uint32_t h2scale(uint32_t w, __half2 s) {
    __half2 a = *(__half2*)&w;
    a = __hmul2(a, s);
    return *(uint32_t*)&a;
}
// packed (lo,hi) f32 -> f16x2, then 2^x approx
__device__ __forceinline__ uint32_t exp2_h2(float lo, float hi) {
    uint32_t packed, r;
    asm("cvt.rn.f16x2.f32 %0, %1, %2;" : "=r"(packed) : "f"(hi), "f"(lo));
    asm("ex2.approx.f16x2 %0, %1;" : "=r"(r) : "r"(packed));
    return r;
}

// ---------------------------------------------------------------------------
// Fused weight conversion (one launch)
// ---------------------------------------------------------------------------
__global__ __launch_bounds__(256) void wconv_all(
    const float* __restrict__ Wq, const float* __restrict__ Wk,
    const float* __restrict__ Wv, const float* __restrict__ Wo,
    const float* __restrict__ We, const float* __restrict__ Wd,
    __half2* __restrict__ oq, __half2* __restrict__ ok,
    __half2* __restrict__ ov, __half2* __restrict__ oo,
    __half2* __restrict__ oe, __half2* __restrict__ od)
{
    int idx = blockIdx.x * 256 + threadIdx.x;
    const float* W;
    __half2* out;
    int nshift, i;
    if (idx < (1 << 21)) {
        const int m = idx >> 19;
        i = idx & ((1 << 19) - 1);
        W   = (m == 0) ? Wq : (m == 1) ? Wk : (m == 2) ? Wv : Wo;
        out = (m == 0) ? oq : (m == 1) ? ok : (m == 2) ? ov : oo;
        nshift = 10;
    } else if (idx < (2 << 21)) {
        i = idx - (1 << 21);
        W = We; out = oe; nshift = 12;
    } else {
        i = idx - (2 << 21);
        W = Wd; out = od; nshift = 10;
    }
    const int kk = i >> nshift;
    const int n  = i & ((1 << nshift) - 1);
    const size_t base = ((size_t)(2 * kk) << nshift) + n;
    out[i] = __floats2half2_rn(W[base], W[base + ((size_t)1 << nshift)]);
}

// ---------------------------------------------------------------------------
// Fused double LayerNorm -> fp16 out
// ---------------------------------------------------------------------------
__global__ __launch_bounds__(256) void ln2_kernel(
    const float* __restrict__ x,
    const float* __restrict__ ga, const float* __restrict__ ba,
    const float* __restrict__ gb, const float* __restrict__ bb,
    __half* __restrict__ out)
{
    __shared__ float red[16];
    __shared__ float bc[2];
    const int row = blockIdx.x, tid = threadIdx.x;
    const float4 v = *(const float4*)(x + (size_t)row * CD + tid * 4);

    float s  = v.x + v.y + v.z + v.w;
    float s2 = v.x*v.x + v.y*v.y + v.z*v.z + v.w*v.w;
    #pragma unroll
    for (int o = 16; o; o >>= 1) {
        s  += __shfl_xor_sync(~0u, s,  o);
        s2 += __shfl_xor_sync(~0u, s2, o);
    }
    if ((tid & 31) == 0) { red[(tid >> 5)*2] = s; red[(tid >> 5)*2 + 1] = s2; }
    __syncthreads();
    if (tid == 0) {
        float a = 0.f, b2 = 0.f;
        #pragma unroll
        for (int w = 0; w < 8; w++) { a += red[w*2]; b2 += red[w*2 + 1]; }
        float mu  = a * (1.f / CD);
        float var = b2 * (1.f / CD) - mu * mu;
        bc[0] = mu; bc[1] = rsqrtf(var + 1e-5f);
    }
    __syncthreads();
    float mu = bc[0], rstd = bc[1];
    __syncthreads();

    const float4 g4 = *(const float4*)(ga + tid * 4);
    const float4 b4 = *(const float4*)(ba + tid * 4);
    float y[4];
    y[0] = (v.x - mu) * rstd * g4.x + b4.x;
    y[1] = (v.y - mu) * rstd * g4.y + b4.y;
    y[2] = (v.z - mu) * rstd * g4.z + b4.z;
    y[3] = (v.w - mu) * rstd * g4.w + b4.w;

    s  = y[0] + y[1] + y[2] + y[3];
    s2 = y[0]*y[0] + y[1]*y[1] + y[2]*y[2] + y[3]*y[3];
    #pragma unroll
    for (int o = 16; o; o >>= 1) {
        s  += __shfl_xor_sync(~0u, s,  o);
        s2 += __shfl_xor_sync(~0u, s2, o);
    }
    if ((tid & 31) == 0) { red[(tid >> 5)*2] = s; red[(tid >> 5)*2 + 1] = s2; }
    __syncthreads();
    if (tid == 0) {
        float a = 0.f, b2 = 0.f;
        #pragma unroll
        for (int w = 0; w < 8; w++) { a += red[w*2]; b2 += red[w*2 + 1]; }
        float mu2  = a * (1.f / CD);
        float var2 = b2 * (1.f / CD) - mu2 * mu2;
        bc[0] = mu2; bc[1] = rsqrtf(var2 + 1e-5f);
    }
    __syncthreads();
    mu = bc[0]; rstd = bc[1];

    const float4 g24 = *(const float4*)(gb + tid * 4);
    const float4 b24 = *(const float4*)(bb + tid * 4);
    float o0 = (y[0] - mu) * rstd * g24.x + b24.x;
    float o1 = (y[1] - mu) * rstd * g24.y + b24.y;
    float o2 = (y[2] - mu) * rstd * g24.z + b24.z;
    float o3 = (y[3] - mu) * rstd * g24.w + b24.w;
    __half* op = out + (size_t)row * CD + tid * 4;
    *(__half2*)(op)     = __floats2half2_rn(o0, o1);
    *(__half2*)(op + 2) = __floats2half2_rn(o2, o3);
}

__global__ __launch_bounds__(256) void ln1_kernel(
    const float* __restrict__ x,
    const float* __restrict__ g, const float* __restrict__ b,
    __half* __restrict__ out)
{
    __shared__ float red[16];
    __shared__ float bc[2];
    const int row = blockIdx.x, tid = threadIdx.x;
    const float4 v = *(const float4*)(x + (size_t)row * CD + tid * 4);

    float s  = v.x + v.y + v.z + v.w;
    float s2 = v.x*v.x + v.y*v.y + v.z*v.z + v.w*v.w;
    #pragma unroll
    for (int o = 16; o; o >>= 1) {
        s  += __shfl_xor_sync(~0u, s,  o);
        s2 += __shfl_xor_sync(~0u, s2, o);
    }
    if ((tid & 31) == 0) { red[(tid >> 5)*2] = s; red[(tid >> 5)*2 + 1] = s2; }
    __syncthreads();
    if (tid == 0) {
        float a = 0.f, b2 = 0.f;
        #pragma unroll
        for (int w = 0; w < 8; w++) { a += red[w*2]; b2 += red[w*2 + 1]; }
        float mu  = a * (1.f / CD);
        float var = b2 * (1.f / CD) - mu * mu;
        bc[0] = mu; bc[1] = rsqrtf(var + 1e-5f);
    }
    __syncthreads();
    const float mu = bc[0], rstd = bc[1];
    const float4 g4 = *(const float4*)(g + tid * 4);
    const float4 b4 = *(const float4*)(b + tid * 4);
    float o0 = (v.x - mu) * rstd * g4.x + b4.x;
    float o1 = (v.y - mu) * rstd * g4.y + b4.y;
    float o2 = (v.z - mu) * rstd * g4.z + b4.z;
    float o3 = (v.w - mu) * rstd * g4.w + b4.w;
    __half* op = out + (size_t)row * CD + tid * 4;
    *(__half2*)(op)     = __floats2half2_rn(o0, o1);
    *(__half2*)(op + 2) = __floats2half2_rn(o2, o3);
}

// ---------------------------------------------------------------------------
// FP16 tensor-core GEMM, 4-stage cp.async ring (R15, unchanged)
// ---------------------------------------------------------------------------
#define GH_ASTG 10240u
#define GH_BSTG 8192u
#define GH_SMEM (4 * (GH_ASTG + GH_BSTG))   // 73728

__global__ __launch_bounds__(256, 2) void gemm_h(
    const __half* __restrict__ A,
    const __half2* __restrict__ Wp0, const __half2* __restrict__ Wp1,
    const __half2* __restrict__ Wp2,
    const float* __restrict__ b0, const float* __restrict__ b1,
    const float* __restrict__ b2,
    const float* __restrict__ res,
    float* __restrict__ C0, float* __restrict__ C1, float* __restrict__ C2,
    __half* __restrict__ H0, __half* __restrict__ H1, __half* __restrict__ H2,
    int M, int N, int K, int act)
{
    extern __shared__ uint32_t gsm[];
    uint32_t* Bsm = gsm + 4 * 2560;

    const int z = blockIdx.z;
    const __half2* Wp  = (z == 0) ? Wp0 : (z == 1) ? Wp1 : Wp2;
    const float*  bias = (z == 0) ? b0  : (z == 1) ? b1  : b2;
    float*        Cc   = (z == 0) ? C0  : (z == 1) ? C1  : C2;
    __half*       Hh   = (z == 0) ? H0  : (z == 1) ? H1  : H2;

    const int tid  = threadIdx.x;
    const int lane = tid & 31;
    const int warp = tid >> 5;
    const int wm = warp & 1;
    const int wn = warp >> 1;
    const int bm = blockIdx.y * 128;
    const int bn = blockIdx.x * 128;

    const int ar1 = tid >> 2,          aq1 = tid & 3;
    const int ar2 = (tid + 256) >> 2,  aq2 = (tid + 256) & 3;
    const int bk1 = tid >> 5,          bn1 = tid & 31;
    const int bk2 = (tid + 256) >> 5,  bn2 = (tid + 256) & 31;

    const uint32_t sA = (uint32_t)__cvta_generic_to_shared(gsm);
    const uint32_t sB = sA + 4u * GH_ASTG;
    const uint32_t aD1 = sA + (uint32_t)(ar1 * 20 + aq1 * 4) * 4u;
    const uint32_t aD2 = sA + (uint32_t)(ar2 * 20 + aq2 * 4) * 4u;
    const uint32_t bD1 = sB + (uint32_t)(bk1 * 128 + ((bn1 * 4) ^ (8 * bk1))) * 4u;
    const uint32_t bD2 = sB + (uint32_t)(bk2 * 128 + ((bn2 * 4) ^ (8 * bk2))) * 4u;

    const __half*  gA1 = A + (size_t)(bm + ar1) * K + aq1 * 8;
    const __half*  gA2 = A + (size_t)(bm + ar2) * K + aq2 * 8;
    const __half2* gB1 = Wp + (size_t)bk1 * N + bn + bn1 * 4;
    const __half2* gB2 = Wp + (size_t)bk2 * N + bn + bn2 * 4;
    const size_t bStep = (size_t)16 * N;

    const int mi = lane >> 3;
    const int rr = lane & 7;
    uint32_t aL[4];
    #pragma unroll
    for (int mf = 0; mf < 4; mf++) {
        const int m = wm * 64 + mf * 16 + (mi & 1) * 8 + rr;
        aL[mf] = sA + (uint32_t)(m * 20 + (mi >> 1) * 4) * 4u;
    }

    float acc[4][4][4];
    #pragma unroll
    for (int i = 0; i < 4; i++)
        #pragma unroll
        for (int j = 0; j < 4; j++)
            #pragma unroll
            for (int r = 0; r < 4; r++) acc[i][j][r] = 0.f;

    auto issue = [&](uint32_t slot) {
        cp16(aD1 + slot * GH_ASTG, gA1);
        cp16(aD2 + slot * GH_ASTG, gA2);
        cp16(bD1 + slot * GH_BSTG, gB1);
        cp16(bD2 + slot * GH_BSTG, gB2);
        gA1 += 32; gA2 += 32; gB1 += bStep; gB2 += bStep;
    };

    issue(0); cp_commit();
    issue(1); cp_commit();
    issue(2); cp_commit();
    issue(3); cp_commit();

    const int nK = K >> 5;
    const int r4 = lane >> 2;
    const int c4 = lane & 3;
    const int nb0 = wn * 32 + r4;

    for (int kt = 0; kt < nK; kt += 4) {
        #pragma unroll
        for (int s = 0; s < 4; s++) {
            cp_wait<3>();
            __syncthreads();
            const uint32_t curA = (uint32_t)s * GH_ASTG;
            const uint32_t* Bp = Bsm + s * 2048;

            #pragma unroll
            for (int p = 0; p < 2; p++) {
                uint32_t af[4][4], bf[4][2];
                #pragma unroll
                for (int mf = 0; mf < 4; mf++)
                    ldsm4(af[mf], aL[mf] + curA + (uint32_t)(p * 32));
                #pragma unroll
                for (int nf = 0; nf < 4; nf++) {
                    const int n = nb0 + nf * 8;
                    bf[nf][0] = Bp[(p * 8 + c4) * 128     + (n ^ (64 * p + 8 * c4))];
                    bf[nf][1] = Bp[(p * 8 + c4 + 4) * 128 + (n ^ (64 * p + 8 * c4 + 32))];
                }
                #pragma unroll
                for (int mf = 0; mf < 4; mf++)
                    #pragma unroll
                    for (int nf = 0; nf < 4; nf++)
                        mma_f16(acc[mf][nf], af[mf], bf[nf]);
            }
            __syncthreads();
            if (kt + s + 4 < nK) issue((uint32_t)s);
            cp_commit();
        }
    }

    // epilogue
    #pragma unroll
    for (int mf = 0; mf < 4; mf++) {
        #pragma unroll
        for (int nf = 0; nf < 4; nf++) {
            const int col = bn + wn * 32 + nf * 8 + c4 * 2;
            const float bx = bias[col], by = bias[col + 1];
            #pragma unroll
            for (int h = 0; h < 2; h++) {
                const int row = bm + wm * 64 + mf * 16 + r4 + h * 8;
                float ox = acc[mf][nf][h * 2 + 0] + bx;
                float oy = acc[mf][nf][h * 2 + 1] + by;
                if (act) {
                    ox *= 1.f / (1.f + __expf(-ox));
                    oy *= 1.f / (1.f + __expf(-oy));
                }
                const size_t off = (size_t)row * N + col;
                if (res) {
                    const float2 rr2 = *(const float2*)(res + off);
                    ox += rr2.x; oy += rr2.y;
                }
                if (Cc) {
                    float2 o; o.x = ox; o.y = oy;
                    *(float2*)(Cc + off) = o;
                }
                if (Hh) *(__half2*)(Hh + off) = __floats2half2_rn(ox, oy);
            }
        }
    }
}

// ---------------------------------------------------------------------------
// FP16 flash attention v5: 128-row Q tile, 256 threads, register-resident P,
// ldmatrix K + ldmatrix.trans V, fp16 ex2 softmax, row-sums via P@ones MMA,
// reversed qt mapping for causal load balance.
// ---------------------------------------------------------------------------
#define AST 36
#define ATTN_SMEM ((128*AST + 2*64*AST + 2*64*AST) * 4)

__global__ __launch_bounds__(256, 2) void attn_h(
    const __half* __restrict__ Qh, const __half* __restrict__ Kh,
    const __half* __restrict__ Vh, __half* __restrict__ O)
{
    extern __shared__ uint32_t smA[];
    uint32_t* Qs = smA;
    uint32_t* Ks = Qs + 128 * AST;
    uint32_t* Vs = Ks + 2 * 64 * AST;

    const int bh = blockIdx.y;
    const int b = bh >> 4, h = bh & 15;
    const int qt = gridDim.x - 1 - blockIdx.x;    // heavy CTAs first
    const int q0 = qt * 128;
    const int tid = threadIdx.x;
    const int lane = tid & 31;
    const int warp = tid >> 5;
    const int r4 = lane >> 2;
    const int c4 = lane & 3;

    const __half* qg = Qh + (size_t)(b * TD + q0) * CD + h * HD;
    const __half* kg = Kh + (size_t)b * TD * CD + h * HD;
    const __half* vg = Vh + (size_t)b * TD * CD + h * HD;

    const uint32_t sQ = (uint32_t)__cvta_generic_to_shared(Qs);
    const uint32_t sK = (uint32_t)__cvta_generic_to_shared(Ks);
    const uint32_t sV = (uint32_t)__cvta_generic_to_shared(Vs);

    #pragma unroll
    for (int i = 0; i < 4; i++) {
        const int idx = tid + i * 256;
        const int row = idx >> 3, cc = idx & 7;
        cp16(sQ + (uint32_t)(row * AST + cc * 4) * 4u, qg + row * CD + cc * 8);
    }
    auto issue_kv = [&](int buf, int k0) {
        #pragma unroll
        for (int i = 0; i < 2; i++) {
            const int idx = tid + i * 256;
            const int row = idx >> 3, cc = idx & 7;
            const size_t g = (size_t)(k0 + row) * CD + cc * 8;
            cp16(sK + (uint32_t)(buf * 64 * AST + row * AST + cc * 4) * 4u, kg + g);
            cp16(sV + (uint32_t)(buf * 64 * AST + row * AST + cc * 4) * 4u, vg + g);
        }
    };
    const int nkt = 2 * qt + 2;
    issue_kv(0, 0);
    cp_commit();
    if (nkt > 1) { issue_kv(1, 64); cp_commit(); }

    const uint32_t lmOff  = (uint32_t)((lane & 7) * AST + (lane >> 3) * 4) * 4u;
    const uint32_t lmTOff = (uint32_t)(lane * AST) * 4u;

    uint32_t qf[4][4];
    float oacc[8][4];
    #pragma unroll
    for (int nt = 0; nt < 8; nt++)
        #pragma unroll
        for (int r = 0; r < 4; r++) oacc[nt][r] = 0.f;
    float m0 = -1e30f, m1 = -1e30f, l0 = 0.f, l1 = 0.f;

    const __half2 sc = __float2half2_rn(0.125f * 1.4426950408889634f);
    const int wrow = warp * 16;
    const int grow = q0 + wrow;
    const uint32_t onesf[2] = {0x3C003C00u, 0x3C003C00u};

    for (int kt = 0; kt < nkt; kt++) {
        if (kt + 1 < nkt) cp_wait<1>(); else cp_wait<0>();
        __syncthreads();
        const int cur = kt & 1;
        const int k0 = kt * 64;
        const uint32_t kBase = sK + (uint32_t)(cur * 64 * AST) * 4u + lmOff;
        const uint32_t vBase = sV + (uint32_t)(cur * 64 * AST) * 4u + lmTOff;

        if (kt == 0) {
            const uint32_t* qp = Qs + (wrow + r4) * AST;
            #pragma unroll
            for (int p = 0; p < 4; p++) {
                qf[p][0] = h2scale(qp[p * 8 + c4], sc);
                qf[p][1] = h2scale(qp[8 * AST + p * 8 + c4], sc);
                qf[p][2] = h2scale(qp[p * 8 + c4 + 4], sc);
                qf[p][3] = h2scale(qp[8 * AST + p * 8 + c4 + 4], sc);
            }
        }

        if (k0 <= grow + 15) {
            // ---- S = Q K^T (log2 domain) ----
            float sacc[8][4];
            #pragma unroll
            for (int nt = 0; nt < 8; nt++)
                #pragma unroll
                for (int r = 0; r < 4; r++) sacc[nt][r] = 0.f;

            #pragma unroll
            for (int nt = 0; nt < 8; nt++) {
                uint32_t k01[4], k23[4];
                const uint32_t a = kBase + (uint32_t)(nt * 8 * AST) * 4u;
                ldsm4(k01, a);
                ldsm4(k23, a + 64u);
                mma_f16(sacc[nt], qf[0], &k01[0]);
                mma_f16(sacc[nt], qf[1], &k01[2]);
                mma_f16(sacc[nt], qf[2], &k23[0]);
                mma_f16(sacc[nt], qf[3], &k23[2]);
            }

            if (k0 + 63 > grow) {
                const int row0 = grow + r4;
                #pragma unroll
                for (int nt = 0; nt < 8; nt++) {
                    const int cb = k0 + nt * 8 + 2 * c4;
                    if (cb + 0 > row0)     sacc[nt][0] = -1e30f;
                    if (cb + 1 > row0)     sacc[nt][1] = -1e30f;
                    if (cb + 0 > row0 + 8) sacc[nt][2] = -1e30f;
                    if (cb + 1 > row0 + 8) sacc[nt][3] = -1e30f;
                }
            }

            // ---- online softmax: max reduce, fp16 ex2, l via P@ones ----
            float rm0 = -1e30f, rm1 = -1e30f;
            #pragma unroll
            for (int nt = 0; nt < 8; nt++) {
                rm0 = fmaxf(rm0, fmaxf(sacc[nt][0], sacc[nt][1]));
                rm1 = fmaxf(rm1, fmaxf(sacc[nt][2], sacc[nt][3]));
            }
            rm0 = fmaxf(rm0, __shfl_xor_sync(~0u, rm0, 1));
            rm0 = fmaxf(rm0, __shfl_xor_sync(~0u, rm0, 2));
            rm1 = fmaxf(rm1, __shfl_xor_sync(~0u, rm1, 1));
            rm1 = fmaxf(rm1, __shfl_xor_sync(~0u, rm1, 2));

            const float mn0 = fmaxf(m0, rm0), mn1 = fmaxf(m1, rm1);
            const float f0 = exp2f(m0 - mn0), f1 = exp2f(m1 - mn1);
            m0 = mn0; m1 = mn1;

            uint32_t af[4][4];
            #pragma unroll
            for (int p = 0; p < 4; p++) {
                const int ntA = 2 * p, ntB = 2 * p + 1;
                af[p][0] = exp2_h2(sacc[ntA][0] - mn0, sacc[ntA][1] - mn0);
                af[p][1] = exp2_h2(sacc[ntA][2] - mn1, sacc[ntA][3] - mn1);
                af[p][2] = exp2_h2(sacc[ntB][0] - mn0, sacc[ntB][1] - mn0);
                af[p][3] = exp2_h2(sacc[ntB][2] - mn1, sacc[ntB][3] - mn1);
            }

            // l += P @ ones (exact f32 row sums of the fp16 P)
            float lacc[4] = {0.f, 0.f, 0.f, 0.f};
            #pragma unroll
            for (int p = 0; p < 4; p++)
                mma_f16(lacc, af[p], onesf);
            l0 = l0 * f0 + lacc[0];
            l1 = l1 * f1 + lacc[2];

            #pragma unroll
            for (int nt = 0; nt < 8; nt++) {
                oacc[nt][0] *= f0; oacc[nt][1] *= f0;
                oacc[nt][2] *= f1; oacc[nt][3] *= f1;
            }

            // ---- O += P V (V via ldmatrix.trans) ----
            #pragma unroll
            for (int nt = 0; nt < 8; nt++) {
                uint32_t v0[4], v1[4];
                const uint32_t a = vBase + (uint32_t)(nt * 4) * 4u;
                ldsm4t(v0, a);                                    // keys 0..31
                ldsm4t(v1, a + (uint32_t)(32 * AST) * 4u);        // keys 32..63
                mma_f16(oacc[nt], af[0], &v0[0]);
                mma_f16(oacc[nt], af[1], &v0[2]);
                mma_f16(oacc[nt], af[2], &v1[0]);
                mma_f16(oacc[nt], af[3], &v1[2]);
            }
        }

        __syncthreads();
        if (kt + 2 < nkt) { issue_kv(cur, (kt + 2) * 64); cp_commit(); }
    }

    const float inv0 = 1.f / l0, inv1 = 1.f / l1;
    const int row0 = grow + r4;
    #pragma unroll
    for (int nt = 0; nt < 8; nt++) {
        const int col = h * HD + nt * 8 + 2 * c4;
        *(__half2*)(O + (size_t)(b * TD + row0) * CD + col) =
            __floats2half2_rn(oacc[nt][0] * inv0, oacc[nt][1] * inv0);
        *(__half2*)(O + (size_t)(b * TD + row0 + 8) * CD + col) =
            __floats2half2_rn(oacc[nt][2] * inv1, oacc[nt][3] * inv1);
    }
}

// ---------------------------------------------------------------------------
// Launch
// ---------------------------------------------------------------------------
extern "C" void kernel_launch(void* const* d_in, const int* in_sizes, int n_in,
                              void* d_out, int out_size)
{
    const float* x      = (const float*)d_in[0];
    const float* ln_a_g = (const float*)d_in[1];
    const float* ln_a_b = (const float*)d_in[2];
    const float* ln_b_g = (const float*)d_in[3];
    const float* ln_b_b = (const float*)d_in[4];
    const float* ln_c_g = (const float*)d_in[5];
    const float* ln_c_b = (const float*)d_in[6];
    const float* Wq = (const float*)d_in[7];  const float* bq = (const float*)d_in[8];
    const float* Wk = (const float*)d_in[9];  const float* bk = (const float*)d_in[10];
    const float* Wv = (const float*)d_in[11]; const float* bv = (const float*)d_in[12];
    const float* Wo = (const float*)d_in[13]; const float* bo = (const float*)d_in[14];
    const float* We = (const float*)d_in[15]; const float* be = (const float*)d_in[16];
    const float* Wd = (const float*)d_in[17]; const float* bd = (const float*)d_in[18];
    float* out = (float*)d_out;

    float *x2;
    __half *th, *t2h, *qh, *kh, *vh, *ctxh, *hh;
    __half2 *wqp, *wkp, *wvp, *wop, *wep, *wdp;
    cudaGetSymbolAddress((void**)&x2,   g_x2);
    cudaGetSymbolAddress((void**)&th,   g_th);
    cudaGetSymbolAddress((void**)&t2h,  g_t2h);
    cudaGetSymbolAddress((void**)&qh,   g_qh);
    cudaGetSymbolAddress((void**)&kh,   g_kh);
    cudaGetSymbolAddress((void**)&vh,   g_vh);
    cudaGetSymbolAddress((void**)&ctxh, g_ctxh);
    cudaGetSymbolAddress((void**)&hh,   g_hh);
    cudaGetSymbolAddress((void**)&wqp,  g_wqp);
    cudaGetSymbolAddress((void**)&wkp,  g_wkp);
    cudaGetSymbolAddress((void**)&wvp,  g_wvp);
    cudaGetSymbolAddress((void**)&wop,  g_wop);
    cudaGetSymbolAddress((void**)&wep,  g_wep);
    cudaGetSymbolAddress((void**)&wdp,  g_wdp);

    cudaFuncSetAttribute(attn_h, cudaFuncAttributeMaxDynamicSharedMemorySize,
                         ATTN_SMEM);
    cudaFuncSetAttribute(attn_h, cudaFuncAttributePreferredSharedMemoryCarveout,
                         100);
    cudaFuncSetAttribute(gemm_h, cudaFuncAttributeMaxDynamicSharedMemorySize,
                         GH_SMEM);
    cudaFuncSetAttribute(gemm_h, cudaFuncAttributePreferredSharedMemoryCarveout,
                         100);

    // 0. fused weight conversion
    {
        const int total = 3 * (1 << 21);
        wconv_all<<<total / 256, 256>>>(Wq, Wk, Wv, Wo, We, Wd,
                                        wqp, wkp, wvp, wop, wep, wdp);
    }

    // 1. th = fp16(LN_b(LN_a(x)))
    ln2_kernel<<<NT, 256>>>(x, ln_a_g, ln_a_b, ln_b_g, ln_b_b, th);

    // 2. QKV (fused)
    {
        dim3 grid(CD / 128, NT / 128, 3);
        gemm_h<<<grid, 256, GH_SMEM>>>(th, wqp, wkp, wvp, bq, bk, bv, nullptr,
                                       nullptr, nullptr, nullptr,
                                       qh, kh, vh, NT, CD, CD, 0);
    }

    // 3. causal attention -> ctxh
    {
        dim3 grid(TD / 128, BD * HN);
        attn_h<<<grid, 256, ATTN_SMEM>>>(qh, kh, vh, ctxh);
    }

    // 4. x2 = x + ctx @ Wo + bo
    {
        dim3 grid(CD / 128, NT / 128, 1);
        gemm_h<<<grid, 256, GH_SMEM>>>(ctxh, wop, wop, wop, bo, bo, bo, x,
                                       x2, x2, x2, nullptr, nullptr, nullptr,
                                       NT, CD, CD, 0);
    }

    // 5. t2h = fp16(LN_c(x2))
    ln1_kernel<<<NT, 256>>>(x2, ln_c_g, ln_c_b, t2h);

    // 6. hh = fp16(silu(t2 @ We + be))
    {
        dim3 grid(DFFD / 128, NT / 128, 1);
        gemm_h<<<grid, 256, GH_SMEM>>>(t2h, wep, wep, wep, be, be, be, nullptr,
                                       nullptr, nullptr, nullptr, hh, hh, hh,
                                       NT, DFFD, CD, 1);
    }

    // 7. out = x2 + h @ Wd + bd
    {
        dim3 grid(CD / 128, NT / 128, 1);
        gemm_h<<<grid, 256, GH_SMEM>>>(hh, wdp, wdp, wdp, bd, bd, bd, x2,
                                       out, out, out, nullptr, nullptr, nullptr,
                                       NT, CD, DFFD, 0);
    }
}